// round 12
// baseline (speedup 1.0000x reference)
#include <cuda_runtime.h>
#include <cuda_bf16.h>
#include <math.h>
#include <stdint.h>

#define B_    2
#define T_    2048
#define D_    2048
#define H_    16
#define KVH_  4
#define HD_   128
#define NTOK  (B_*T_)

// ---------------- scratch (device globals: allocation-free) ----------------
__device__ float g_q  [NTOK*D_];
__device__ float g_k  [NTOK*KVH_*HD_];
__device__ float g_v  [NTOK*KVH_*HD_];
__device__ float g_g  [NTOK*D_];
__device__ float g_o  [NTOK*D_];
// split-bf16 operands
__device__ __align__(16) __nv_bfloat16 g_ah [NTOK*D_];
__device__ __align__(16) __nv_bfloat16 g_al [NTOK*D_];
__device__ __align__(16) __nv_bfloat16 g_akh[NTOK*D_];
__device__ __align__(16) __nv_bfloat16 g_akl[NTOK*D_];
__device__ __align__(16) __nv_bfloat16 g_avh[NTOK*D_];
__device__ __align__(16) __nv_bfloat16 g_avl[NTOK*D_];
__device__ __align__(16) __nv_bfloat16 g_wth [2*D_*D_];
__device__ __align__(16) __nv_bfloat16 g_wtl [2*D_*D_];
__device__ __align__(16) __nv_bfloat16 g_wkth[512*D_];
__device__ __align__(16) __nv_bfloat16 g_wktl[512*D_];
__device__ __align__(16) __nv_bfloat16 g_wvth[512*D_];
__device__ __align__(16) __nv_bfloat16 g_wvtl[512*D_];
// pre-split attention operands
__device__ __align__(16) __nv_bfloat16 g_qh [NTOK*D_];
__device__ __align__(16) __nv_bfloat16 g_ql [NTOK*D_];
__device__ __align__(16) __nv_bfloat16 g_kh [NTOK*KVH_*HD_];
__device__ __align__(16) __nv_bfloat16 g_kl [NTOK*KVH_*HD_];
__device__ __align__(16) __nv_bfloat16 g_vh [NTOK*KVH_*HD_];
__device__ __align__(16) __nv_bfloat16 g_vl [NTOK*KVH_*HD_];

// ================= baseline-ISA helpers =================
__device__ __forceinline__ uint32_t smem_u32(const void* p) {
    uint32_t a;
    asm("{ .reg .u64 t; cvta.to.shared.u64 t, %1; cvt.u32.u64 %0, t; }" : "=r"(a) : "l"(p));
    return a;
}
__device__ __forceinline__ uint32_t sw128(uint32_t off) { return off ^ ((off >> 3) & 0x70); }
__device__ __forceinline__ uint32_t sw256(uint32_t off) { return off ^ ((off >> 4) & 0x70); }

__device__ __forceinline__ void cp_async16(uint32_t dst, const void* src) {
    asm volatile("cp.async.cg.shared.global [%0], [%1], 16;" :: "r"(dst), "l"(src) : "memory");
}
#define CP_COMMIT() asm volatile("cp.async.commit_group;" ::: "memory")
#define CP_WAIT(n)  asm volatile("cp.async.wait_group %0;" :: "n"(n) : "memory")

__device__ __forceinline__ void ldsm_x4(uint32_t* r, uint32_t addr) {
    asm volatile("ldmatrix.sync.aligned.m8n8.x4.shared.b16 {%0,%1,%2,%3}, [%4];"
                 : "=r"(r[0]), "=r"(r[1]), "=r"(r[2]), "=r"(r[3]) : "r"(addr));
}
__device__ __forceinline__ void ldsm_x4_t(uint32_t* r, uint32_t addr) {
    asm volatile("ldmatrix.sync.aligned.m8n8.x4.trans.shared.b16 {%0,%1,%2,%3}, [%4];"
                 : "=r"(r[0]), "=r"(r[1]), "=r"(r[2]), "=r"(r[3]) : "r"(addr));
}
__device__ __forceinline__ void mma16816(float* d, const uint32_t* a, const uint32_t* b) {
    asm volatile("mma.sync.aligned.m16n8k16.row.col.f32.bf16.bf16.f32 "
                 "{%0,%1,%2,%3}, {%4,%5,%6,%7}, {%8,%9}, {%0,%1,%2,%3};"
                 : "+f"(d[0]), "+f"(d[1]), "+f"(d[2]), "+f"(d[3])
                 : "r"(a[0]), "r"(a[1]), "r"(a[2]), "r"(a[3]), "r"(b[0]), "r"(b[1]));
}

// fast exp on the FMA pipe
__device__ __forceinline__ float fast_exp(float x) {
    x = fmaxf(x, -80.f);
    const float LOG2E = 1.4426950408889634f;
    float t = x * LOG2E;
    float r = t + 12582912.f;
    float i = r - 12582912.f;
    float f = t - i;
    uint32_t ib = __float_as_uint(r);
    float sc = __uint_as_float((ib + 127u) << 23);
    float p = 1.3333558146e-3f;
    p = fmaf(p, f, 9.6181291076e-3f);
    p = fmaf(p, f, 5.5504108664e-2f);
    p = fmaf(p, f, 2.4022650696e-1f);
    p = fmaf(p, f, 6.9314718056e-1f);
    p = fmaf(p, f, 1.0f);
    return p * sc;
}

__device__ __forceinline__ void split2(float a, float b, uint32_t& hp, uint32_t& lp) {
    __nv_bfloat16 ha = __float2bfloat16(a), hb = __float2bfloat16(b);
    __nv_bfloat16 la = __float2bfloat16(a - __bfloat162float(ha));
    __nv_bfloat16 lb = __float2bfloat16(b - __bfloat162float(hb));
    hp = ((uint32_t)__bfloat16_as_ushort(hb) << 16) | __bfloat16_as_ushort(ha);
    lp = ((uint32_t)__bfloat16_as_ushort(lb) << 16) | __bfloat16_as_ushort(la);
}

// ================= elementwise kernels =================
// fused: time-shift mix + split for k/v paths, plus plain split for xq
__global__ void mix_split_kernel(const float* __restrict__ xq,
                                 const float* __restrict__ xk, const float* __restrict__ xv,
                                 const float* __restrict__ mk, const float* __restrict__ mv,
                                 __nv_bfloat16* __restrict__ qh2, __nv_bfloat16* __restrict__ ql2,
                                 __nv_bfloat16* __restrict__ kh, __nv_bfloat16* __restrict__ kl,
                                 __nv_bfloat16* __restrict__ vh, __nv_bfloat16* __restrict__ vl)
{
    const int D4 = D_ / 4;
    int idx = blockIdx.x * blockDim.x + threadIdx.x;
    int d4  = idx & (D4 - 1);
    int tok = idx >> 9;
    int t   = tok & (T_ - 1);

    // xq split
    {
        float4 v = ((const float4*)xq)[idx];
        uint32_t h0, l0, h1, l1;
        split2(v.x, v.y, h0, l0);
        split2(v.z, v.w, h1, l1);
        ((uint2*)qh2)[idx] = make_uint2(h0, h1);
        ((uint2*)ql2)[idx] = make_uint2(l0, l1);
    }

    float4 kc = ((const float4*)xk)[idx];
    float4 vc = ((const float4*)xv)[idx];
    float4 m1 = ((const float4*)mk)[d4];
    float4 m2 = ((const float4*)mv)[d4];
    float4 kp = make_float4(0.f,0.f,0.f,0.f);
    float4 vp = make_float4(0.f,0.f,0.f,0.f);
    if (t > 0) {
        kp = ((const float4*)xk)[idx - D4];
        vp = ((const float4*)xv)[idx - D4];
    }
    float4 r1, r2;
    r1.x = kc.x + m1.x*(kp.x-kc.x);  r1.y = kc.y + m1.y*(kp.y-kc.y);
    r1.z = kc.z + m1.z*(kp.z-kc.z);  r1.w = kc.w + m1.w*(kp.w-kc.w);
    r2.x = vc.x + m2.x*(vp.x-vc.x);  r2.y = vc.y + m2.y*(vp.y-vc.y);
    r2.z = vc.z + m2.z*(vp.z-vc.z);  r2.w = vc.w + m2.w*(vp.w-vc.w);

    uint32_t h0, l0, h1, l1;
    split2(r1.x, r1.y, h0, l0);  split2(r1.z, r1.w, h1, l1);
    ((uint2*)kh)[idx] = make_uint2(h0, h1);
    ((uint2*)kl)[idx] = make_uint2(l0, l1);
    split2(r2.x, r2.y, h0, l0);  split2(r2.z, r2.w, h1, l1);
    ((uint2*)vh)[idx] = make_uint2(h0, h1);
    ((uint2*)vl)[idx] = make_uint2(l0, l1);
}

// W[K=2048, N] -> Wt_hi/lo [N, 2048] transposed split; vectorized 8B stores.
__global__ void wsplit_t_kernel(const float* __restrict__ W,
                                __nv_bfloat16* __restrict__ th,
                                __nv_bfloat16* __restrict__ tl, int N)
{
    __shared__ float s[32][132];
    const int k0 = blockIdx.y * 128, n0 = blockIdx.x * 32;
    const int tx = threadIdx.x, ty = threadIdx.y;
    const int tid = ty * 32 + tx;

#pragma unroll
    for (int i = 0; i < 4; i++) {
        int kk = ty + 32*i;
        s[tx][kk] = W[(size_t)(k0 + kk) * N + n0 + tx];
    }
    __syncthreads();

    const int r = tid >> 5, seg = tid & 31;
    float4 v = *(const float4*)(&s[r][seg << 2]);
    uint32_t h0, l0, h1, l1;
    split2(v.x, v.y, h0, l0);
    split2(v.z, v.w, h1, l1);
    size_t o = ((size_t)(n0 + r) * D_ + k0 + (seg << 2)) >> 2;
    ((uint2*)th)[o] = make_uint2(h0, h1);
    ((uint2*)tl)[o] = make_uint2(l0, l1);
}

#define GK  2048
#define NCH (GK/64)

// ================= BIG split-bf16 GEMM body (256x128 block, 64x64 warps) ===
#define BG_A     32768
#define BG_B     16384
#define BG_STAGE (2*BG_A + 2*BG_B)
#define BG_SMEM  (2*BG_STAGE + 1024)

__device__ __forceinline__ void gemm_big_body(
    const __nv_bfloat16* __restrict__ ah, const __nv_bfloat16* __restrict__ al,
    const __nv_bfloat16* __restrict__ wth, const __nv_bfloat16* __restrict__ wtl,
    float* __restrict__ C0, float* __restrict__ C1, int cstride,
    int m0, int n0, char* sm)
{
    const uint32_t smb   = smem_u32(sm);
    const uint32_t tiles = (smb + 1023u) & ~1023u;

    const int tid  = threadIdx.x;
    const int wid  = tid >> 5, lane = tid & 31;
    const int wm   = wid & 3,  wn   = wid >> 2;

    const __nv_bfloat16* pAh = ah  + (size_t)m0 * GK;
    const __nv_bfloat16* pAl = al  + (size_t)m0 * GK;
    const __nv_bfloat16* pBh = wth + (size_t)n0 * GK;
    const __nv_bfloat16* pBl = wtl + (size_t)n0 * GK;

    float acc[4][8][4];
#pragma unroll
    for (int i = 0; i < 4; i++)
#pragma unroll
        for (int j = 0; j < 8; j++)
#pragma unroll
            for (int q = 0; q < 4; q++) acc[i][j][q] = 0.f;

    auto prefetch = [&](int ch) {
        const uint32_t stage = tiles + (uint32_t)(ch & 1) * BG_STAGE;
        const int ke = ch << 6;
#pragma unroll
        for (int j = 0; j < 8; j++) {
            int idx = tid + (j << 8);
            int r = idx >> 3, c = idx & 7;
            uint32_t off = sw128((r << 7) + (c << 4));
            const size_t go = (size_t)r * GK + ke + (c << 3);
            cp_async16(stage + off,        pAh + go);
            cp_async16(stage + BG_A + off, pAl + go);
        }
#pragma unroll
        for (int j = 0; j < 4; j++) {
            int idx = tid + (j << 8);
            int r = idx >> 3, c = idx & 7;
            uint32_t off = sw128((r << 7) + (c << 4));
            const size_t go = (size_t)r * GK + ke + (c << 3);
            cp_async16(stage + 2*BG_A + off,        pBh + go);
            cp_async16(stage + 2*BG_A + BG_B + off, pBl + go);
        }
        CP_COMMIT();
    };

    prefetch(0);

    for (int ch = 0; ch < NCH; ch++) {
        if (ch + 1 < NCH) { prefetch(ch + 1); CP_WAIT(1); }
        else              { CP_WAIT(0); }
        __syncthreads();

        const uint32_t stage = tiles + (uint32_t)(ch & 1) * BG_STAGE;
        const uint32_t sAh = stage,          sAl = stage + BG_A;
        const uint32_t sBh = stage + 2*BG_A, sBl = stage + 2*BG_A + BG_B;

#pragma unroll
        for (int ks = 0; ks < 4; ks++) {
            const int kb = ks << 5;

            uint32_t ahf[4][4], alf[4][4];
#pragma unroll
            for (int mt = 0; mt < 4; mt++) {
                int row = wm*64 + mt*16 + (lane & 15);
                uint32_t off = sw128((uint32_t)(row << 7) + kb + ((lane >> 4) << 4));
                ldsm_x4(ahf[mt], sAh + off);
                ldsm_x4(alf[mt], sAl + off);
            }
            const int brow = wn*64 + (lane & 7) + ((lane >> 4) << 3);
            const int bko  = kb + (((lane >> 3) & 1) << 4);
#pragma unroll
            for (int np = 0; np < 4; np++) {
                uint32_t bh[4], bl[4];
                uint32_t off = sw128((uint32_t)((brow + np*16) << 7) + bko);
                ldsm_x4(bh, sBh + off);
                ldsm_x4(bl, sBl + off);
#pragma unroll
                for (int mt = 0; mt < 4; mt++) {
                    mma16816(acc[mt][2*np],   ahf[mt], bh);
                    mma16816(acc[mt][2*np+1], ahf[mt], bh + 2);
                }
#pragma unroll
                for (int mt = 0; mt < 4; mt++) {
                    mma16816(acc[mt][2*np],   ahf[mt], bl);
                    mma16816(acc[mt][2*np+1], ahf[mt], bl + 2);
                }
#pragma unroll
                for (int mt = 0; mt < 4; mt++) {
                    mma16816(acc[mt][2*np],   alf[mt], bh);
                    mma16816(acc[mt][2*np+1], alf[mt], bh + 2);
                }
            }
        }
        __syncthreads();
    }

    float* C = C0;
    int nc = n0;
    if (C1 != nullptr && n0 >= cstride) { C = C1; nc = n0 - cstride; }

    const int er = lane >> 2, ec = (lane & 3) << 1;
#pragma unroll
    for (int mt = 0; mt < 4; mt++) {
        int r0 = m0 + wm*64 + mt*16 + er;
#pragma unroll
        for (int nt = 0; nt < 8; nt++) {
            int c = nc + wn*64 + nt*8 + ec;
            *(float2*)(C + (size_t)r0      * cstride + c) = make_float2(acc[mt][nt][0], acc[mt][nt][1]);
            *(float2*)(C + (size_t)(r0 + 8)* cstride + c) = make_float2(acc[mt][nt][2], acc[mt][nt][3]);
        }
    }
}

// standalone big GEMM (Wo projection)
__global__ void __launch_bounds__(256, 1) gemm_mma_big(
    const __nv_bfloat16* __restrict__ ah, const __nv_bfloat16* __restrict__ al,
    const __nv_bfloat16* __restrict__ wth, const __nv_bfloat16* __restrict__ wtl,
    float* __restrict__ C0, float* __restrict__ C1, int cstride)
{
    extern __shared__ char sm[];
    gemm_big_body(ah, al, wth, wtl, C0, C1, cstride,
                  blockIdx.y << 8, blockIdx.x << 7, sm);
}

// fused q/k/v projection GEMM: flat tile index over 3 jobs
#define QKV_TILES 640
__global__ void __launch_bounds__(256, 1) gemm_mma_qkv(
    const __nv_bfloat16* __restrict__ aqh, const __nv_bfloat16* __restrict__ aql,
    const __nv_bfloat16* __restrict__ akh, const __nv_bfloat16* __restrict__ akl,
    const __nv_bfloat16* __restrict__ avh, const __nv_bfloat16* __restrict__ avl,
    const __nv_bfloat16* __restrict__ wqh, const __nv_bfloat16* __restrict__ wql,
    const __nv_bfloat16* __restrict__ wkh, const __nv_bfloat16* __restrict__ wkl,
    const __nv_bfloat16* __restrict__ wvh, const __nv_bfloat16* __restrict__ wvl,
    float* __restrict__ pq, float* __restrict__ pg,
    float* __restrict__ pk, float* __restrict__ pv)
{
    extern __shared__ char sm[];
    const int idx = blockIdx.x;
    if (idx < 512) {
        gemm_big_body(aqh, aql, wqh, wql, pq, pg, D_,
                      (idx >> 5) << 8, (idx & 31) << 7, sm);
    } else if (idx < 576) {
        const int i = idx - 512;
        gemm_big_body(akh, akl, wkh, wkl, pk, nullptr, 512,
                      (i >> 2) << 8, (i & 3) << 7, sm);
    } else {
        const int i = idx - 576;
        gemm_big_body(avh, avl, wvh, wvl, pv, nullptr, 512,
                      (i >> 2) << 8, (i & 3) << 7, sm);
    }
}

// ---- fused per-head RMS norm (+RoPE) for q, k, v in ONE launch ----
__device__ __forceinline__ void norm_head_body(
    const float* __restrict__ x, int heads, int do_rope, float scale,
    __nv_bfloat16* __restrict__ oh, __nv_bfloat16* __restrict__ ol, int blk)
{
    __shared__ float sbuf[4];
    __shared__ float svals[128];
    const int head = blk % heads;
    const int tok  = blk / heads;
    const int t    = tok % T_;
    const size_t base = (size_t)tok*heads*HD_ + head*HD_;
    const float* p = x + base;
    const int d = threadIdx.x;

    float v  = p[d];
    float ss = v*v;
#pragma unroll
    for (int o = 16; o > 0; o >>= 1) ss += __shfl_xor_sync(0xffffffffu, ss, o);
    if ((d & 31) == 0) sbuf[d >> 5] = ss;
    __syncthreads();
    float tot = sbuf[0] + sbuf[1] + sbuf[2] + sbuf[3];
    float r   = rsqrtf(tot * (1.f/HD_) + 1e-8f);
    float vn  = v * r;
    float f;

    if (do_rope) {
        svals[d] = vn;
        __syncthreads();
        int   j  = d & 63;
        float inv_freq = exp2f(-(float)j * (13.287712379549449f / 64.f));
        float ang = (float)t * inv_freq;
        float sn, cs;
        sincosf(ang, &sn, &cs);
        float partner = svals[d ^ 64];
        f = (d < 64) ? (vn*cs - partner*sn) : (vn*cs + partner*sn);
    } else {
        f = vn;
    }
    f *= scale;
    __nv_bfloat16 h = __float2bfloat16(f);
    __nv_bfloat16 l = __float2bfloat16(f - __bfloat162float(h));
    oh[base + d] = h;
    ol[base + d] = l;
}

#define NQBLK (NTOK*H_)
#define NKBLK (NTOK*KVH_)
__global__ void norm_all_kernel(
    const float* __restrict__ pq, const float* __restrict__ pk, const float* __restrict__ pv,
    __nv_bfloat16* __restrict__ qh, __nv_bfloat16* __restrict__ ql,
    __nv_bfloat16* __restrict__ kh, __nv_bfloat16* __restrict__ kl,
    __nv_bfloat16* __restrict__ vh, __nv_bfloat16* __restrict__ vl)
{
    const int blk = blockIdx.x;
    if (blk < NQBLK) {
        norm_head_body(pq, H_, 1, 0.08838834764831845f, qh, ql, blk);
    } else if (blk < NQBLK + NKBLK) {
        norm_head_body(pk, KVH_, 1, 1.f, kh, kl, blk - NQBLK);
    } else {
        norm_head_body(pv, KVH_, 0, 1.f, vh, vl, blk - NQBLK - NKBLK);
    }
}

// ================= flash attention via mma.sync (Q frags hoisted) ==========
#define FQH  0
#define FQL  32768
#define FKV  65536
#define FSTG 65536
#define FLASH_SMEM (FKV + 2*FSTG)

__global__ void __launch_bounds__(256, 1) flash_mma_kernel(
    const __nv_bfloat16* __restrict__ qh, const __nv_bfloat16* __restrict__ ql,
    const __nv_bfloat16* __restrict__ kh, const __nv_bfloat16* __restrict__ kl,
    const __nv_bfloat16* __restrict__ vh, const __nv_bfloat16* __restrict__ vl,
    const float* __restrict__ g,
    __nv_bfloat16* __restrict__ oh_out, __nv_bfloat16* __restrict__ ol_out)
{
    extern __shared__ char sm[];
    const uint32_t smb = smem_u32(sm);

    const int tid  = threadIdx.x;
    const int w    = tid >> 5, lane = tid & 31;
    const int qt   = (gridDim.x - 1) - blockIdx.x;   // LPT: heavy tiles first
    const int b    = blockIdx.y >> 4;
    const int h    = blockIdx.y & 15;
    const int kvh  = h >> 2;
    const int qs   = qt << 7;

    // ---- async load Q tile (group 0) ----
    {
        const __nv_bfloat16* qgh = qh + ((size_t)(b*T_ + qs))*D_ + h*HD_;
        const __nv_bfloat16* qgl = ql + ((size_t)(b*T_ + qs))*D_ + h*HD_;
#pragma unroll
        for (int it = 0; it < 8; it++) {
            int idx = tid + (it << 8);
            int r = idx >> 4, c = idx & 15;
            uint32_t off = sw256((r << 8) + (c << 4));
            cp_async16(smb + FQH + off, qgh + (size_t)r*D_ + (c << 3));
            cp_async16(smb + FQL + off, qgl + (size_t)r*D_ + (c << 3));
        }
        CP_COMMIT();
    }

    const __nv_bfloat16* kh_b = kh + (size_t)(b*T_)*(KVH_*HD_) + kvh*HD_;
    const __nv_bfloat16* kl_b = kl + (size_t)(b*T_)*(KVH_*HD_) + kvh*HD_;
    const __nv_bfloat16* vh_b = vh + (size_t)(b*T_)*(KVH_*HD_) + kvh*HD_;
    const __nv_bfloat16* vl_b = vl + (size_t)(b*T_)*(KVH_*HD_) + kvh*HD_;

    auto prefetch_kv = [&](int kt) {
        const uint32_t sb = smb + FKV + (uint32_t)(kt & 1)*FSTG;
        const size_t rb = (size_t)(kt << 6) * (KVH_*HD_);
        const __nv_bfloat16* ps[4] = { kh_b + rb, kl_b + rb, vh_b + rb, vl_b + rb };
#pragma unroll
        for (int t = 0; t < 4; t++) {
#pragma unroll
            for (int it = 0; it < 4; it++) {
                int idx = tid + (it << 8);
                int r = idx >> 4, c = idx & 15;
                cp_async16(sb + t*16384 + sw256((r << 8) + (c << 4)),
                           ps[t] + (size_t)r*(KVH_*HD_) + (c << 3));
            }
        }
        CP_COMMIT();
    };

    prefetch_kv(0);

    // ---- hoist Q fragments into registers (FIFO: group 0 = Q done) ----
    uint32_t aQh[8][4], aQl[8][4];
    CP_WAIT(1);
    __syncthreads();
#pragma unroll
    for (int ks8 = 0; ks8 < 8; ks8++) {
        int row = (w << 4) + (lane & 15);
        uint32_t off = sw256((uint32_t)(row << 8) + (ks8 << 5) + ((lane >> 4) << 4));
        ldsm_x4(aQh[ks8], smb + FQH + off);
        ldsm_x4(aQl[ks8], smb + FQL + off);
    }

    float o[16][4];
#pragma unroll
    for (int nh = 0; nh < 16; nh++)
#pragma unroll
        for (int qq = 0; qq < 4; qq++) o[nh][qq] = 0.f;
    float m0 = -1e30f, m1 = -1e30f, l0 = 0.f, l1 = 0.f;

    const int nkv = 2*qt + 2;
    for (int kt = 0; kt < nkv; kt++) {
        const int ks = kt << 6;
        if (kt + 1 < nkv) { prefetch_kv(kt + 1); CP_WAIT(1); }
        else              { CP_WAIT(0); }
        __syncthreads();

        const uint32_t sb  = smb + FKV + (uint32_t)(kt & 1)*FSTG;
        const uint32_t sKH = sb, sKL = sb + 16384, sVH = sb + 32768, sVL = sb + 49152;

        // ---- S = Q K^T (term-major, Q from regs) ----
        float s[8][4];
#pragma unroll
        for (int nt = 0; nt < 8; nt++)
#pragma unroll
            for (int qq = 0; qq < 4; qq++) s[nt][qq] = 0.f;

#pragma unroll
        for (int ks8 = 0; ks8 < 8; ks8++) {
            const int kb = ks8 << 5;
            uint32_t bhf[4][4], blf[4][4];
            const int brow4 = (lane & 7) + ((lane >> 4) << 3);
            const int bko   = kb + (((lane >> 3) & 1) << 4);
#pragma unroll
            for (int np = 0; np < 4; np++) {
                uint32_t off = sw256((uint32_t)((brow4 + np*16) << 8) + bko);
                ldsm_x4(bhf[np], sKH + off);
                ldsm_x4(blf[np], sKL + off);
            }
#pragma unroll
            for (int np = 0; np < 4; np++) {
                mma16816(s[2*np],   aQh[ks8], bhf[np]);
                mma16816(s[2*np+1], aQh[ks8], bhf[np] + 2);
            }
#pragma unroll
            for (int np = 0; np < 4; np++) {
                mma16816(s[2*np],   aQh[ks8], blf[np]);
                mma16816(s[2*np+1], aQh[ks8], blf[np] + 2);
            }
#pragma unroll
            for (int np = 0; np < 4; np++) {
                mma16816(s[2*np],   aQl[ks8], bhf[np]);
                mma16816(s[2*np+1], aQl[ks8], bhf[np] + 2);
            }
        }

        // ---- causal mask ----
        if (kt >= 2*qt) {
            const int gr0 = qs + (w << 4) + (lane >> 2);
            const int gc0 = ks + ((lane & 3) << 1);
#pragma unroll
            for (int nt = 0; nt < 8; nt++) {
                int c = gc0 + nt*8;
                if (c     > gr0)     s[nt][0] = -1e30f;
                if (c + 1 > gr0)     s[nt][1] = -1e30f;
                if (c     > gr0 + 8) s[nt][2] = -1e30f;
                if (c + 1 > gr0 + 8) s[nt][3] = -1e30f;
            }
        }

        // ---- online softmax ----
        float mx0 = -1e30f, mx1 = -1e30f;
#pragma unroll
        for (int nt = 0; nt < 8; nt++) {
            mx0 = fmaxf(mx0, fmaxf(s[nt][0], s[nt][1]));
            mx1 = fmaxf(mx1, fmaxf(s[nt][2], s[nt][3]));
        }
        mx0 = fmaxf(mx0, __shfl_xor_sync(0xffffffffu, mx0, 1));
        mx0 = fmaxf(mx0, __shfl_xor_sync(0xffffffffu, mx0, 2));
        mx1 = fmaxf(mx1, __shfl_xor_sync(0xffffffffu, mx1, 1));
        mx1 = fmaxf(mx1, __shfl_xor_sync(0xffffffffu, mx1, 2));
        float m0n = fmaxf(m0, mx0), m1n = fmaxf(m1, mx1);
        float sc0 = fast_exp(m0 - m0n), sc1 = fast_exp(m1 - m1n);
        m0 = m0n; m1 = m1n;

        float sum0 = 0.f, sum1 = 0.f;
#pragma unroll
        for (int nt = 0; nt < 8; nt++) {
            s[nt][0] = fast_exp(s[nt][0] - m0n); sum0 += s[nt][0];
            s[nt][1] = fast_exp(s[nt][1] - m0n); sum0 += s[nt][1];
            s[nt][2] = fast_exp(s[nt][2] - m1n); sum1 += s[nt][2];
            s[nt][3] = fast_exp(s[nt][3] - m1n); sum1 += s[nt][3];
        }
        sum0 += __shfl_xor_sync(0xffffffffu, sum0, 1);
        sum0 += __shfl_xor_sync(0xffffffffu, sum0, 2);
        sum1 += __shfl_xor_sync(0xffffffffu, sum1, 1);
        sum1 += __shfl_xor_sync(0xffffffffu, sum1, 2);
        l0 = l0*sc0 + sum0;
        l1 = l1*sc1 + sum1;

#pragma unroll
        for (int nh = 0; nh < 16; nh++) {
            o[nh][0] *= sc0; o[nh][1] *= sc0;
            o[nh][2] *= sc1; o[nh][3] *= sc1;
        }

        // ---- O += P V (term-major) ----
#pragma unroll
        for (int j = 0; j < 4; j++) {
            uint32_t aPh[4], aPl[4];
            split2(s[2*j][0],   s[2*j][1],   aPh[0], aPl[0]);
            split2(s[2*j][2],   s[2*j][3],   aPh[1], aPl[1]);
            split2(s[2*j+1][0], s[2*j+1][1], aPh[2], aPl[2]);
            split2(s[2*j+1][2], s[2*j+1][3], aPh[3], aPl[3]);
            const uint32_t vrow = (j << 4) + (lane & 15);
            const uint32_t nsel = (lane >> 4);
#pragma unroll
            for (int pp = 0; pp < 4; pp++) {
                uint32_t bh0[4], bl0[4], bh1[4], bl1[4];
                uint32_t off0 = sw256((vrow << 8) + ((4*pp     + nsel) << 4));
                uint32_t off1 = sw256((vrow << 8) + ((4*pp + 2 + nsel) << 4));
                ldsm_x4_t(bh0, sVH + off0);
                ldsm_x4_t(bl0, sVL + off0);
                ldsm_x4_t(bh1, sVH + off1);
                ldsm_x4_t(bl1, sVL + off1);
                mma16816(o[4*pp],   aPh, bh0);
                mma16816(o[4*pp+1], aPh, bh0 + 2);
                mma16816(o[4*pp+2], aPh, bh1);
                mma16816(o[4*pp+3], aPh, bh1 + 2);
                mma16816(o[4*pp],   aPl, bh0);
                mma16816(o[4*pp+1], aPl, bh0 + 2);
                mma16816(o[4*pp+2], aPl, bh1);
                mma16816(o[4*pp+3], aPl, bh1 + 2);
                mma16816(o[4*pp],   aPh, bl0);
                mma16816(o[4*pp+1], aPh, bl0 + 2);
                mma16816(o[4*pp+2], aPh, bl1);
                mma16816(o[4*pp+3], aPh, bl1 + 2);
            }
        }
        __syncthreads();
    }

    // ---- fused epilogue: 1/l, per-head L2 norm, gate, split-bf16 out ----
    const float inv0 = 1.f / l0, inv1 = 1.f / l1;
    float y0[16][2], y1[16][2];
    float ss0 = 0.f, ss1 = 0.f;
#pragma unroll
    for (int nh = 0; nh < 16; nh++) {
        y0[nh][0] = o[nh][0]*inv0;  y0[nh][1] = o[nh][1]*inv0;
        y1[nh][0] = o[nh][2]*inv1;  y1[nh][1] = o[nh][3]*inv1;
        ss0 += y0[nh][0]*y0[nh][0] + y0[nh][1]*y0[nh][1];
        ss1 += y1[nh][0]*y1[nh][0] + y1[nh][1]*y1[nh][1];
    }
    ss0 += __shfl_xor_sync(0xffffffffu, ss0, 1);
    ss0 += __shfl_xor_sync(0xffffffffu, ss0, 2);
    ss1 += __shfl_xor_sync(0xffffffffu, ss1, 1);
    ss1 += __shfl_xor_sync(0xffffffffu, ss1, 2);
    const float s0 = 1.f / fmaxf(sqrtf(ss0), 1e-12f);
    const float s1 = 1.f / fmaxf(sqrtf(ss1), 1e-12f);

    const int r0 = qs + (w << 4) + (lane >> 2);
    const size_t base0 = ((size_t)(b*T_) + r0)*D_ + h*HD_ + ((lane & 3) << 1);
    const size_t base1 = base0 + (size_t)8*D_;
#pragma unroll
    for (int nh = 0; nh < 16; nh++) {
        float2 gv0 = *(const float2*)(g + base0 + nh*8);
        float2 gv1 = *(const float2*)(g + base1 + nh*8);
        uint32_t hp, lp;
        split2(gv0.x*y0[nh][0]*s0, gv0.y*y0[nh][1]*s0, hp, lp);
        *(uint32_t*)(oh_out + base0 + nh*8) = hp;
        *(uint32_t*)(ol_out + base0 + nh*8) = lp;
        split2(gv1.x*y1[nh][0]*s1, gv1.y*y1[nh][1]*s1, hp, lp);
        *(uint32_t*)(oh_out + base1 + nh*8) = hp;
        *(uint32_t*)(ol_out + base1 + nh*8) = lp;
    }
}

// ---------------- final RMS norm over D, scaled by 1/sqrt(48) ----------------
__global__ void final_norm_kernel(const float* __restrict__ in, float* __restrict__ out)
{
    __shared__ float sbuf[8];
    const int tok = blockIdx.x;
    const float* p = in + (size_t)tok*D_;
    const int base = threadIdx.x * 8;

    float4 a = *(const float4*)(p + base);
    float4 b = *(const float4*)(p + base + 4);
    float ss = a.x*a.x + a.y*a.y + a.z*a.z + a.w*a.w
             + b.x*b.x + b.y*b.y + b.z*b.z + b.w*b.w;
#pragma unroll
    for (int o = 16; o > 0; o >>= 1) ss += __shfl_xor_sync(0xffffffffu, ss, o);
    if ((threadIdx.x & 31) == 0) sbuf[threadIdx.x >> 5] = ss;
    __syncthreads();
    float tot = 0.f;
#pragma unroll
    for (int i = 0; i < 8; i++) tot += sbuf[i];
    float r = rsqrtf(tot * (1.f/D_) + 1e-8f) * 0.14433756729740643f;

    float* q = out + (size_t)tok*D_;
    a.x*=r; a.y*=r; a.z*=r; a.w*=r;
    b.x*=r; b.y*=r; b.z*=r; b.w*=r;
    *(float4*)(q + base)     = a;
    *(float4*)(q + base + 4) = b;
}

// ---------------- launcher ----------------
extern "C" void kernel_launch(void* const* d_in, const int* in_sizes, int n_in,
                              void* d_out, int out_size)
{
    (void)in_sizes; (void)n_in; (void)out_size;
    const float* xq = (const float*)d_in[0];
    const float* xk = (const float*)d_in[1];
    const float* xv = (const float*)d_in[2];
    const float* Wq = (const float*)d_in[3];
    const float* Wk = (const float*)d_in[4];
    const float* Wv = (const float*)d_in[5];
    const float* Wg = (const float*)d_in[6];
    const float* Wo = (const float*)d_in[7];
    const float* mk = (const float*)d_in[8];
    const float* mv = (const float*)d_in[9];
    float* out = (float*)d_out;

    float *pq, *pk, *pv, *pg, *po;
    __nv_bfloat16 *pah, *pal, *pakh, *pakl, *pavh, *pavl, *pwth, *pwtl;
    __nv_bfloat16 *pwkh, *pwkl, *pwvh, *pwvl;
    __nv_bfloat16 *pqh, *pql, *pkh, *pkl, *pvh, *pvl;
    cudaGetSymbolAddress((void**)&pq,   g_q);
    cudaGetSymbolAddress((void**)&pk,   g_k);
    cudaGetSymbolAddress((void**)&pv,   g_v);
    cudaGetSymbolAddress((void**)&pg,   g_g);
    cudaGetSymbolAddress((void**)&po,   g_o);
    cudaGetSymbolAddress((void**)&pah,  g_ah);
    cudaGetSymbolAddress((void**)&pal,  g_al);
    cudaGetSymbolAddress((void**)&pakh, g_akh);
    cudaGetSymbolAddress((void**)&pakl, g_akl);
    cudaGetSymbolAddress((void**)&pavh, g_avh);
    cudaGetSymbolAddress((void**)&pavl, g_avl);
    cudaGetSymbolAddress((void**)&pwth, g_wth);
    cudaGetSymbolAddress((void**)&pwtl, g_wtl);
    cudaGetSymbolAddress((void**)&pwkh, g_wkth);
    cudaGetSymbolAddress((void**)&pwkl, g_wktl);
    cudaGetSymbolAddress((void**)&pwvh, g_wvth);
    cudaGetSymbolAddress((void**)&pwvl, g_wvtl);
    cudaGetSymbolAddress((void**)&pqh,  g_qh);
    cudaGetSymbolAddress((void**)&pql,  g_ql);
    cudaGetSymbolAddress((void**)&pkh,  g_kh);
    cudaGetSymbolAddress((void**)&pkl,  g_kl);
    cudaGetSymbolAddress((void**)&pvh,  g_vh);
    cudaGetSymbolAddress((void**)&pvl,  g_vl);

    cudaFuncSetAttribute(gemm_mma_big, cudaFuncAttributeMaxDynamicSharedMemorySize,
                         BG_SMEM);
    cudaFuncSetAttribute(gemm_mma_qkv, cudaFuncAttributeMaxDynamicSharedMemorySize,
                         BG_SMEM);
    cudaFuncSetAttribute(flash_mma_kernel, cudaFuncAttributeMaxDynamicSharedMemorySize,
                         FLASH_SMEM);

    const int XS_GRID = (NTOK*D_/4)/256;
    dim3 wgrid_full(D_/32, D_/128), wgrid_kv(512/32, D_/128), wblk(32, 32);

    // 1) fused mix/split (xq, xk, xv) + weight transposes
    mix_split_kernel<<<XS_GRID, 256>>>(xq, xk, xv, mk, mv,
                                       pah, pal, pakh, pakl, pavh, pavl);
    wsplit_t_kernel<<<wgrid_full, wblk>>>(Wq, pwth, pwtl, D_);
    wsplit_t_kernel<<<wgrid_full, wblk>>>(Wg, pwth + (size_t)D_*D_, pwtl + (size_t)D_*D_, D_);
    wsplit_t_kernel<<<wgrid_kv, wblk>>>(Wk, pwkh, pwkl, 512);
    wsplit_t_kernel<<<wgrid_kv, wblk>>>(Wv, pwvh, pwvl, 512);

    // 2) fused q/k/v/g projections: single 640-tile launch
    gemm_mma_qkv<<<QKV_TILES, 256, BG_SMEM>>>(
        pah, pal, pakh, pakl, pavh, pavl,
        pwth, pwtl, pwkh, pwkl, pwvh, pwvl,
        pq, pg, pk, pv);

    // 3) fused per-head RMS norm (+RoPE) for q,k,v in one launch
    norm_all_kernel<<<NQBLK + 2*NKBLK, 128>>>(pq, pk, pv,
                                              pqh, pql, pkh, pkl, pvh, pvl);

    // 4) causal GQA attention + fused L2-norm/gate/split epilogue
    flash_mma_kernel<<<dim3(T_/128, B_*H_), 256, FLASH_SMEM>>>(
        pqh, pql, pkh, pkl, pvh, pvl, pg, pah, pal);

    // 5) output projection
    wsplit_t_kernel<<<wgrid_full, wblk>>>(Wo, pwth, pwtl, D_);
    gemm_mma_big<<<dim3(D_/128, NTOK/256), 256, BG_SMEM>>>(
        pah, pal, pwth, pwtl, po, nullptr, D_);

    // 6) final RMS norm + 1/sqrt(2*N_LAYER)
    final_norm_kernel<<<NTOK, 256>>>(po, out);
}

// round 13
// speedup vs baseline: 1.3260x; 1.3260x over previous
#include <cuda_runtime.h>
#include <cuda_fp16.h>
#include <math.h>
#include <stdint.h>

#define B_    2
#define T_    2048
#define D_    2048
#define H_    16
#define KVH_  4
#define HD_   128
#define NTOK  (B_*T_)

// ---------------- scratch (device globals: allocation-free) ----------------
__device__ float g_q  [NTOK*D_];
__device__ float g_k  [NTOK*KVH_*HD_];
__device__ float g_v  [NTOK*KVH_*HD_];
__device__ float g_g  [NTOK*D_];
__device__ float g_o  [NTOK*D_];
// split-fp16 A-side operands (hi+lo), single-fp16 B-side (weights)
__device__ __align__(16) __half g_ah [NTOK*D_];
__device__ __align__(16) __half g_al [NTOK*D_];
__device__ __align__(16) __half g_akh[NTOK*D_];
__device__ __align__(16) __half g_akl[NTOK*D_];
__device__ __align__(16) __half g_avh[NTOK*D_];
__device__ __align__(16) __half g_avl[NTOK*D_];
__device__ __align__(16) __half g_wth [2*D_*D_];
__device__ __align__(16) __half g_wkth[512*D_];
__device__ __align__(16) __half g_wvth[512*D_];
// attention operands: Q split (A-side), K/V single (B-side)
__device__ __align__(16) __half g_qh [NTOK*D_];
__device__ __align__(16) __half g_ql [NTOK*D_];
__device__ __align__(16) __half g_kh [NTOK*KVH_*HD_];
__device__ __align__(16) __half g_vh [NTOK*KVH_*HD_];

// ================= baseline-ISA helpers =================
__device__ __forceinline__ uint32_t smem_u32(const void* p) {
    uint32_t a;
    asm("{ .reg .u64 t; cvta.to.shared.u64 t, %1; cvt.u32.u64 %0, t; }" : "=r"(a) : "l"(p));
    return a;
}
__device__ __forceinline__ uint32_t sw128(uint32_t off) { return off ^ ((off >> 3) & 0x70); }
__device__ __forceinline__ uint32_t sw256(uint32_t off) { return off ^ ((off >> 4) & 0x70); }

__device__ __forceinline__ void cp_async16(uint32_t dst, const void* src) {
    asm volatile("cp.async.cg.shared.global [%0], [%1], 16;" :: "r"(dst), "l"(src) : "memory");
}
#define CP_COMMIT() asm volatile("cp.async.commit_group;" ::: "memory")
#define CP_WAIT(n)  asm volatile("cp.async.wait_group %0;" :: "n"(n) : "memory")

__device__ __forceinline__ void ldsm_x4(uint32_t* r, uint32_t addr) {
    asm volatile("ldmatrix.sync.aligned.m8n8.x4.shared.b16 {%0,%1,%2,%3}, [%4];"
                 : "=r"(r[0]), "=r"(r[1]), "=r"(r[2]), "=r"(r[3]) : "r"(addr));
}
__device__ __forceinline__ void ldsm_x4_t(uint32_t* r, uint32_t addr) {
    asm volatile("ldmatrix.sync.aligned.m8n8.x4.trans.shared.b16 {%0,%1,%2,%3}, [%4];"
                 : "=r"(r[0]), "=r"(r[1]), "=r"(r[2]), "=r"(r[3]) : "r"(addr));
}
__device__ __forceinline__ void mma16816(float* d, const uint32_t* a, const uint32_t* b) {
    asm volatile("mma.sync.aligned.m16n8k16.row.col.f32.f16.f16.f32 "
                 "{%0,%1,%2,%3}, {%4,%5,%6,%7}, {%8,%9}, {%0,%1,%2,%3};"
                 : "+f"(d[0]), "+f"(d[1]), "+f"(d[2]), "+f"(d[3])
                 : "r"(a[0]), "r"(a[1]), "r"(a[2]), "r"(a[3]), "r"(b[0]), "r"(b[1]));
}

// fast exp on the FMA pipe
__device__ __forceinline__ float fast_exp(float x) {
    x = fmaxf(x, -80.f);
    const float LOG2E = 1.4426950408889634f;
    float t = x * LOG2E;
    float r = t + 12582912.f;
    float i = r - 12582912.f;
    float f = t - i;
    uint32_t ib = __float_as_uint(r);
    float sc = __uint_as_float((ib + 127u) << 23);
    float p = 1.3333558146e-3f;
    p = fmaf(p, f, 9.6181291076e-3f);
    p = fmaf(p, f, 5.5504108664e-2f);
    p = fmaf(p, f, 2.4022650696e-1f);
    p = fmaf(p, f, 6.9314718056e-1f);
    p = fmaf(p, f, 1.0f);
    return p * sc;
}

// split two floats into packed fp16x2 hi / lo (A-side exact split)
__device__ __forceinline__ void split2h(float a, float b, uint32_t& hp, uint32_t& lp) {
    __half ha = __float2half_rn(a), hb = __float2half_rn(b);
    __half la = __float2half_rn(a - __half2float(ha));
    __half lb = __float2half_rn(b - __half2float(hb));
    hp = ((uint32_t)__half_as_ushort(hb) << 16) | __half_as_ushort(ha);
    lp = ((uint32_t)__half_as_ushort(lb) << 16) | __half_as_ushort(la);
}
// pack two floats into fp16x2 (B-side single rounding)
__device__ __forceinline__ uint32_t pack2h(float a, float b) {
    __half ha = __float2half_rn(a), hb = __float2half_rn(b);
    return ((uint32_t)__half_as_ushort(hb) << 16) | __half_as_ushort(ha);
}

// ================= elementwise kernels =================
// fused: xq split + time-shift mix + split for k/v paths
__global__ void mix_split_kernel(const float* __restrict__ xq,
                                 const float* __restrict__ xk, const float* __restrict__ xv,
                                 const float* __restrict__ mk, const float* __restrict__ mv,
                                 __half* __restrict__ qh2, __half* __restrict__ ql2,
                                 __half* __restrict__ kh, __half* __restrict__ kl,
                                 __half* __restrict__ vh, __half* __restrict__ vl)
{
    const int D4 = D_ / 4;
    int idx = blockIdx.x * blockDim.x + threadIdx.x;
    int d4  = idx & (D4 - 1);
    int tok = idx >> 9;
    int t   = tok & (T_ - 1);

    {
        float4 v = ((const float4*)xq)[idx];
        uint32_t h0, l0, h1, l1;
        split2h(v.x, v.y, h0, l0);
        split2h(v.z, v.w, h1, l1);
        ((uint2*)qh2)[idx] = make_uint2(h0, h1);
        ((uint2*)ql2)[idx] = make_uint2(l0, l1);
    }

    float4 kc = ((const float4*)xk)[idx];
    float4 vc = ((const float4*)xv)[idx];
    float4 m1 = ((const float4*)mk)[d4];
    float4 m2 = ((const float4*)mv)[d4];
    float4 kp = make_float4(0.f,0.f,0.f,0.f);
    float4 vp = make_float4(0.f,0.f,0.f,0.f);
    if (t > 0) {
        kp = ((const float4*)xk)[idx - D4];
        vp = ((const float4*)xv)[idx - D4];
    }
    float4 r1, r2;
    r1.x = kc.x + m1.x*(kp.x-kc.x);  r1.y = kc.y + m1.y*(kp.y-kc.y);
    r1.z = kc.z + m1.z*(kp.z-kc.z);  r1.w = kc.w + m1.w*(kp.w-kc.w);
    r2.x = vc.x + m2.x*(vp.x-vc.x);  r2.y = vc.y + m2.y*(vp.y-vc.y);
    r2.z = vc.z + m2.z*(vp.z-vc.z);  r2.w = vc.w + m2.w*(vp.w-vc.w);

    uint32_t h0, l0, h1, l1;
    split2h(r1.x, r1.y, h0, l0);  split2h(r1.z, r1.w, h1, l1);
    ((uint2*)kh)[idx] = make_uint2(h0, h1);
    ((uint2*)kl)[idx] = make_uint2(l0, l1);
    split2h(r2.x, r2.y, h0, l0);  split2h(r2.z, r2.w, h1, l1);
    ((uint2*)vh)[idx] = make_uint2(h0, h1);
    ((uint2*)vl)[idx] = make_uint2(l0, l1);
}

// W[K=2048, N] -> Wt [N, 2048] transposed, single fp16
__global__ void wsplit_t_kernel(const float* __restrict__ W,
                                __half* __restrict__ th, int N)
{
    __shared__ float s[32][132];
    const int k0 = blockIdx.y * 128, n0 = blockIdx.x * 32;
    const int tx = threadIdx.x, ty = threadIdx.y;
    const int tid = ty * 32 + tx;

#pragma unroll
    for (int i = 0; i < 4; i++) {
        int kk = ty + 32*i;
        s[tx][kk] = W[(size_t)(k0 + kk) * N + n0 + tx];
    }
    __syncthreads();

    const int r = tid >> 5, seg = tid & 31;
    float4 v = *(const float4*)(&s[r][seg << 2]);
    uint32_t h0 = pack2h(v.x, v.y);
    uint32_t h1 = pack2h(v.z, v.w);
    size_t o = ((size_t)(n0 + r) * D_ + k0 + (seg << 2)) >> 2;
    ((uint2*)th)[o] = make_uint2(h0, h1);
}

#define GK  2048
#define NCH (GK/64)

// ================= BIG GEMM body: 256x128 block, 64x64 warps, 2-term fp16 ==
#define BG_A     32768                    /* 256 rows x 128B */
#define BG_B     16384                    /* 128 rows x 128B */
#define BG_STAGE (2*BG_A + BG_B)          /* 80 KB */
#define BG_SMEM  (2*BG_STAGE + 1024)

__device__ __forceinline__ void gemm_big_body(
    const __half* __restrict__ ah, const __half* __restrict__ al,
    const __half* __restrict__ wth,
    float* __restrict__ C0, float* __restrict__ C1, int cstride,
    int m0, int n0, char* sm)
{
    const uint32_t smb   = smem_u32(sm);
    const uint32_t tiles = (smb + 1023u) & ~1023u;

    const int tid  = threadIdx.x;
    const int wid  = tid >> 5, lane = tid & 31;
    const int wm   = wid & 3,  wn   = wid >> 2;

    const __half* pAh = ah  + (size_t)m0 * GK;
    const __half* pAl = al  + (size_t)m0 * GK;
    const __half* pB  = wth + (size_t)n0 * GK;

    float acc[4][8][4];
#pragma unroll
    for (int i = 0; i < 4; i++)
#pragma unroll
        for (int j = 0; j < 8; j++)
#pragma unroll
            for (int q = 0; q < 4; q++) acc[i][j][q] = 0.f;

    auto prefetch = [&](int ch) {
        const uint32_t stage = tiles + (uint32_t)(ch & 1) * BG_STAGE;
        const int ke = ch << 6;
#pragma unroll
        for (int j = 0; j < 8; j++) {
            int idx = tid + (j << 8);
            int r = idx >> 3, c = idx & 7;
            uint32_t off = sw128((r << 7) + (c << 4));
            const size_t go = (size_t)r * GK + ke + (c << 3);
            cp_async16(stage + off,        pAh + go);
            cp_async16(stage + BG_A + off, pAl + go);
        }
#pragma unroll
        for (int j = 0; j < 4; j++) {
            int idx = tid + (j << 8);
            int r = idx >> 3, c = idx & 7;
            uint32_t off = sw128((r << 7) + (c << 4));
            cp_async16(stage + 2*BG_A + off, pB + (size_t)r * GK + ke + (c << 3));
        }
        CP_COMMIT();
    };

    prefetch(0);

    for (int ch = 0; ch < NCH; ch++) {
        if (ch + 1 < NCH) { prefetch(ch + 1); CP_WAIT(1); }
        else              { CP_WAIT(0); }
        __syncthreads();

        const uint32_t stage = tiles + (uint32_t)(ch & 1) * BG_STAGE;
        const uint32_t sAh = stage, sAl = stage + BG_A, sB = stage + 2*BG_A;

#pragma unroll
        for (int ks = 0; ks < 4; ks++) {
            const int kb = ks << 5;

            uint32_t ahf[4][4], alf[4][4];
#pragma unroll
            for (int mt = 0; mt < 4; mt++) {
                int row = wm*64 + mt*16 + (lane & 15);
                uint32_t off = sw128((uint32_t)(row << 7) + kb + ((lane >> 4) << 4));
                ldsm_x4(ahf[mt], sAh + off);
                ldsm_x4(alf[mt], sAl + off);
            }
            const int brow = wn*64 + (lane & 7) + ((lane >> 4) << 3);
            const int bko  = kb + (((lane >> 3) & 1) << 4);
#pragma unroll
            for (int np = 0; np < 4; np++) {
                uint32_t bh[4];
                uint32_t off = sw128((uint32_t)((brow + np*16) << 7) + bko);
                ldsm_x4(bh, sB + off);
                // pass 1: hi*B
#pragma unroll
                for (int mt = 0; mt < 4; mt++) {
                    mma16816(acc[mt][2*np],   ahf[mt], bh);
                    mma16816(acc[mt][2*np+1], ahf[mt], bh + 2);
                }
                // pass 2: lo*B
#pragma unroll
                for (int mt = 0; mt < 4; mt++) {
                    mma16816(acc[mt][2*np],   alf[mt], bh);
                    mma16816(acc[mt][2*np+1], alf[mt], bh + 2);
                }
            }
        }
        __syncthreads();
    }

    float* C = C0;
    int nc = n0;
    if (C1 != nullptr && n0 >= cstride) { C = C1; nc = n0 - cstride; }

    const int er = lane >> 2, ec = (lane & 3) << 1;
#pragma unroll
    for (int mt = 0; mt < 4; mt++) {
        int r0 = m0 + wm*64 + mt*16 + er;
#pragma unroll
        for (int nt = 0; nt < 8; nt++) {
            int c = nc + wn*64 + nt*8 + ec;
            *(float2*)(C + (size_t)r0      * cstride + c) = make_float2(acc[mt][nt][0], acc[mt][nt][1]);
            *(float2*)(C + (size_t)(r0 + 8)* cstride + c) = make_float2(acc[mt][nt][2], acc[mt][nt][3]);
        }
    }
}

// standalone big GEMM (Wo projection)
__global__ void __launch_bounds__(256, 1) gemm_mma_big(
    const __half* __restrict__ ah, const __half* __restrict__ al,
    const __half* __restrict__ wth,
    float* __restrict__ C0, float* __restrict__ C1, int cstride)
{
    extern __shared__ char sm[];
    gemm_big_body(ah, al, wth, C0, C1, cstride,
                  blockIdx.y << 8, blockIdx.x << 7, sm);
}

// fused q/k/v projection GEMM: flat tile index over 3 jobs
#define QKV_TILES 640
__global__ void __launch_bounds__(256, 1) gemm_mma_qkv(
    const __half* __restrict__ aqh, const __half* __restrict__ aql,
    const __half* __restrict__ akh, const __half* __restrict__ akl,
    const __half* __restrict__ avh, const __half* __restrict__ avl,
    const __half* __restrict__ wqh, const __half* __restrict__ wkh,
    const __half* __restrict__ wvh,
    float* __restrict__ pq, float* __restrict__ pg,
    float* __restrict__ pk, float* __restrict__ pv)
{
    extern __shared__ char sm[];
    const int idx = blockIdx.x;
    if (idx < 512) {
        gemm_big_body(aqh, aql, wqh, pq, pg, D_,
                      (idx >> 5) << 8, (idx & 31) << 7, sm);
    } else if (idx < 576) {
        const int i = idx - 512;
        gemm_big_body(akh, akl, wkh, pk, nullptr, 512,
                      (i >> 2) << 8, (i & 3) << 7, sm);
    } else {
        const int i = idx - 576;
        gemm_big_body(avh, avl, wvh, pv, nullptr, 512,
                      (i >> 2) << 8, (i & 3) << 7, sm);
    }
}

// ---- fused per-head RMS norm (+RoPE), q -> split, k/v -> single ----
__device__ __forceinline__ void norm_head_body(
    const float* __restrict__ x, int heads, int do_rope, float scale,
    __half* __restrict__ oh, __half* __restrict__ ol, int emit_lo, int blk)
{
    __shared__ float sbuf[4];
    __shared__ float svals[128];
    const int head = blk % heads;
    const int tok  = blk / heads;
    const int t    = tok % T_;
    const size_t base = (size_t)tok*heads*HD_ + head*HD_;
    const float* p = x + base;
    const int d = threadIdx.x;

    float v  = p[d];
    float ss = v*v;
#pragma unroll
    for (int o = 16; o > 0; o >>= 1) ss += __shfl_xor_sync(0xffffffffu, ss, o);
    if ((d & 31) == 0) sbuf[d >> 5] = ss;
    __syncthreads();
    float tot = sbuf[0] + sbuf[1] + sbuf[2] + sbuf[3];
    float r   = rsqrtf(tot * (1.f/HD_) + 1e-8f);
    float vn  = v * r;
    float f;

    if (do_rope) {
        svals[d] = vn;
        __syncthreads();
        int   j  = d & 63;
        float inv_freq = exp2f(-(float)j * (13.287712379549449f / 64.f));
        float ang = (float)t * inv_freq;
        float sn, cs;
        sincosf(ang, &sn, &cs);
        float partner = svals[d ^ 64];
        f = (d < 64) ? (vn*cs - partner*sn) : (vn*cs + partner*sn);
    } else {
        f = vn;
    }
    f *= scale;
    __half h = __float2half_rn(f);
    oh[base + d] = h;
    if (emit_lo) ol[base + d] = __float2half_rn(f - __half2float(h));
}

#define NQBLK (NTOK*H_)
#define NKBLK (NTOK*KVH_)
__global__ void norm_all_kernel(
    const float* __restrict__ pq, const float* __restrict__ pk, const float* __restrict__ pv,
    __half* __restrict__ qh, __half* __restrict__ ql,
    __half* __restrict__ kh, __half* __restrict__ vh)
{
    const int blk = blockIdx.x;
    if (blk < NQBLK) {
        norm_head_body(pq, H_, 1, 0.08838834764831845f, qh, ql, 1, blk);
    } else if (blk < NQBLK + NKBLK) {
        norm_head_body(pk, KVH_, 1, 1.f, kh, nullptr, 0, blk - NQBLK);
    } else {
        norm_head_body(pv, KVH_, 0, 1.f, vh, nullptr, 0, blk - NQBLK - NKBLK);
    }
}

// ================= flash attention: Q split, K/V single fp16 ==============
#define FQH  0
#define FQL  32768
#define FKV  65536
#define FSTG 32768         /* per stage: KH 16K + VH 16K */
#define FLASH_SMEM (FKV + 2*FSTG)

__global__ void __launch_bounds__(256, 1) flash_mma_kernel(
    const __half* __restrict__ qh, const __half* __restrict__ ql,
    const __half* __restrict__ kh, const __half* __restrict__ vh,
    const float* __restrict__ g,
    __half* __restrict__ oh_out, __half* __restrict__ ol_out)
{
    extern __shared__ char sm[];
    const uint32_t smb = smem_u32(sm);

    const int tid  = threadIdx.x;
    const int w    = tid >> 5, lane = tid & 31;
    const int qt   = (gridDim.x - 1) - blockIdx.x;   // LPT: heavy tiles first
    const int b    = blockIdx.y >> 4;
    const int h    = blockIdx.y & 15;
    const int kvh  = h >> 2;
    const int qs   = qt << 7;

    // ---- async load Q tile (group 0) ----
    {
        const __half* qgh = qh + ((size_t)(b*T_ + qs))*D_ + h*HD_;
        const __half* qgl = ql + ((size_t)(b*T_ + qs))*D_ + h*HD_;
#pragma unroll
        for (int it = 0; it < 8; it++) {
            int idx = tid + (it << 8);
            int r = idx >> 4, c = idx & 15;
            uint32_t off = sw256((r << 8) + (c << 4));
            cp_async16(smb + FQH + off, qgh + (size_t)r*D_ + (c << 3));
            cp_async16(smb + FQL + off, qgl + (size_t)r*D_ + (c << 3));
        }
        CP_COMMIT();
    }

    const __half* kh_b = kh + (size_t)(b*T_)*(KVH_*HD_) + kvh*HD_;
    const __half* vh_b = vh + (size_t)(b*T_)*(KVH_*HD_) + kvh*HD_;

    auto prefetch_kv = [&](int kt) {
        const uint32_t sb = smb + FKV + (uint32_t)(kt & 1)*FSTG;
        const size_t rb = (size_t)(kt << 6) * (KVH_*HD_);
        const __half* ps[2] = { kh_b + rb, vh_b + rb };
#pragma unroll
        for (int t = 0; t < 2; t++) {
#pragma unroll
            for (int it = 0; it < 4; it++) {
                int idx = tid + (it << 8);
                int r = idx >> 4, c = idx & 15;
                cp_async16(sb + t*16384 + sw256((r << 8) + (c << 4)),
                           ps[t] + (size_t)r*(KVH_*HD_) + (c << 3));
            }
        }
        CP_COMMIT();
    };

    prefetch_kv(0);

    // ---- hoist Q fragments into registers ----
    uint32_t aQh[8][4], aQl[8][4];
    CP_WAIT(1);
    __syncthreads();
#pragma unroll
    for (int ks8 = 0; ks8 < 8; ks8++) {
        int row = (w << 4) + (lane & 15);
        uint32_t off = sw256((uint32_t)(row << 8) + (ks8 << 5) + ((lane >> 4) << 4));
        ldsm_x4(aQh[ks8], smb + FQH + off);
        ldsm_x4(aQl[ks8], smb + FQL + off);
    }

    float o[16][4];
#pragma unroll
    for (int nh = 0; nh < 16; nh++)
#pragma unroll
        for (int qq = 0; qq < 4; qq++) o[nh][qq] = 0.f;
    float m0 = -1e30f, m1 = -1e30f, l0 = 0.f, l1 = 0.f;

    const int nkv = 2*qt + 2;
    for (int kt = 0; kt < nkv; kt++) {
        const int ks = kt << 6;
        if (kt + 1 < nkv) { prefetch_kv(kt + 1); CP_WAIT(1); }
        else              { CP_WAIT(0); }
        __syncthreads();

        const uint32_t sb  = smb + FKV + (uint32_t)(kt & 1)*FSTG;
        const uint32_t sKH = sb, sVH = sb + 16384;

        // ---- S = Q K^T (2-term, Q from regs) ----
        float s[8][4];
#pragma unroll
        for (int nt = 0; nt < 8; nt++)
#pragma unroll
            for (int qq = 0; qq < 4; qq++) s[nt][qq] = 0.f;

#pragma unroll
        for (int ks8 = 0; ks8 < 8; ks8++) {
            const int kb = ks8 << 5;
            uint32_t bhf[4][4];
            const int brow4 = (lane & 7) + ((lane >> 4) << 3);
            const int bko   = kb + (((lane >> 3) & 1) << 4);
#pragma unroll
            for (int np = 0; np < 4; np++) {
                uint32_t off = sw256((uint32_t)((brow4 + np*16) << 8) + bko);
                ldsm_x4(bhf[np], sKH + off);
            }
#pragma unroll
            for (int np = 0; np < 4; np++) {
                mma16816(s[2*np],   aQh[ks8], bhf[np]);
                mma16816(s[2*np+1], aQh[ks8], bhf[np] + 2);
            }
#pragma unroll
            for (int np = 0; np < 4; np++) {
                mma16816(s[2*np],   aQl[ks8], bhf[np]);
                mma16816(s[2*np+1], aQl[ks8], bhf[np] + 2);
            }
        }

        // ---- causal mask ----
        if (kt >= 2*qt) {
            const int gr0 = qs + (w << 4) + (lane >> 2);
            const int gc0 = ks + ((lane & 3) << 1);
#pragma unroll
            for (int nt = 0; nt < 8; nt++) {
                int c = gc0 + nt*8;
                if (c     > gr0)     s[nt][0] = -1e30f;
                if (c + 1 > gr0)     s[nt][1] = -1e30f;
                if (c     > gr0 + 8) s[nt][2] = -1e30f;
                if (c + 1 > gr0 + 8) s[nt][3] = -1e30f;
            }
        }

        // ---- online softmax ----
        float mx0 = -1e30f, mx1 = -1e30f;
#pragma unroll
        for (int nt = 0; nt < 8; nt++) {
            mx0 = fmaxf(mx0, fmaxf(s[nt][0], s[nt][1]));
            mx1 = fmaxf(mx1, fmaxf(s[nt][2], s[nt][3]));
        }
        mx0 = fmaxf(mx0, __shfl_xor_sync(0xffffffffu, mx0, 1));
        mx0 = fmaxf(mx0, __shfl_xor_sync(0xffffffffu, mx0, 2));
        mx1 = fmaxf(mx1, __shfl_xor_sync(0xffffffffu, mx1, 1));
        mx1 = fmaxf(mx1, __shfl_xor_sync(0xffffffffu, mx1, 2));
        float m0n = fmaxf(m0, mx0), m1n = fmaxf(m1, mx1);
        float sc0 = fast_exp(m0 - m0n), sc1 = fast_exp(m1 - m1n);
        m0 = m0n; m1 = m1n;

        float sum0 = 0.f, sum1 = 0.f;
#pragma unroll
        for (int nt = 0; nt < 8; nt++) {
            s[nt][0] = fast_exp(s[nt][0] - m0n); sum0 += s[nt][0];
            s[nt][1] = fast_exp(s[nt][1] - m0n); sum0 += s[nt][1];
            s[nt][2] = fast_exp(s[nt][2] - m1n); sum1 += s[nt][2];
            s[nt][3] = fast_exp(s[nt][3] - m1n); sum1 += s[nt][3];
        }
        sum0 += __shfl_xor_sync(0xffffffffu, sum0, 1);
        sum0 += __shfl_xor_sync(0xffffffffu, sum0, 2);
        sum1 += __shfl_xor_sync(0xffffffffu, sum1, 1);
        sum1 += __shfl_xor_sync(0xffffffffu, sum1, 2);
        l0 = l0*sc0 + sum0;
        l1 = l1*sc1 + sum1;

#pragma unroll
        for (int nh = 0; nh < 16; nh++) {
            o[nh][0] *= sc0; o[nh][1] *= sc0;
            o[nh][2] *= sc1; o[nh][3] *= sc1;
        }

        // ---- O += P V (2-term: P split, V single) ----
#pragma unroll
        for (int j = 0; j < 4; j++) {
            uint32_t aPh[4], aPl[4];
            split2h(s[2*j][0],   s[2*j][1],   aPh[0], aPl[0]);
            split2h(s[2*j][2],   s[2*j][3],   aPh[1], aPl[1]);
            split2h(s[2*j+1][0], s[2*j+1][1], aPh[2], aPl[2]);
            split2h(s[2*j+1][2], s[2*j+1][3], aPh[3], aPl[3]);
            const uint32_t vrow = (j << 4) + (lane & 15);
            const uint32_t nsel = (lane >> 4);
#pragma unroll
            for (int pp = 0; pp < 4; pp++) {
                uint32_t bh0[4], bh1[4];
                uint32_t off0 = sw256((vrow << 8) + ((4*pp     + nsel) << 4));
                uint32_t off1 = sw256((vrow << 8) + ((4*pp + 2 + nsel) << 4));
                ldsm_x4_t(bh0, sVH + off0);
                ldsm_x4_t(bh1, sVH + off1);
                mma16816(o[4*pp],   aPh, bh0);
                mma16816(o[4*pp+1], aPh, bh0 + 2);
                mma16816(o[4*pp+2], aPh, bh1);
                mma16816(o[4*pp+3], aPh, bh1 + 2);
                mma16816(o[4*pp],   aPl, bh0);
                mma16816(o[4*pp+1], aPl, bh0 + 2);
                mma16816(o[4*pp+2], aPl, bh1);
                mma16816(o[4*pp+3], aPl, bh1 + 2);
            }
        }
        __syncthreads();
    }

    // ---- fused epilogue: 1/l, per-head L2 norm, gate, split-fp16 out ----
    const float inv0 = 1.f / l0, inv1 = 1.f / l1;
    float y0[16][2], y1[16][2];
    float ss0 = 0.f, ss1 = 0.f;
#pragma unroll
    for (int nh = 0; nh < 16; nh++) {
        y0[nh][0] = o[nh][0]*inv0;  y0[nh][1] = o[nh][1]*inv0;
        y1[nh][0] = o[nh][2]*inv1;  y1[nh][1] = o[nh][3]*inv1;
        ss0 += y0[nh][0]*y0[nh][0] + y0[nh][1]*y0[nh][1];
        ss1 += y1[nh][0]*y1[nh][0] + y1[nh][1]*y1[nh][1];
    }
    ss0 += __shfl_xor_sync(0xffffffffu, ss0, 1);
    ss0 += __shfl_xor_sync(0xffffffffu, ss0, 2);
    ss1 += __shfl_xor_sync(0xffffffffu, ss1, 1);
    ss1 += __shfl_xor_sync(0xffffffffu, ss1, 2);
    const float s0 = 1.f / fmaxf(sqrtf(ss0), 1e-12f);
    const float s1 = 1.f / fmaxf(sqrtf(ss1), 1e-12f);

    const int r0 = qs + (w << 4) + (lane >> 2);
    const size_t base0 = ((size_t)(b*T_) + r0)*D_ + h*HD_ + ((lane & 3) << 1);
    const size_t base1 = base0 + (size_t)8*D_;
#pragma unroll
    for (int nh = 0; nh < 16; nh++) {
        float2 gv0 = *(const float2*)(g + base0 + nh*8);
        float2 gv1 = *(const float2*)(g + base1 + nh*8);
        uint32_t hp, lp;
        split2h(gv0.x*y0[nh][0]*s0, gv0.y*y0[nh][1]*s0, hp, lp);
        *(uint32_t*)(oh_out + base0 + nh*8) = hp;
        *(uint32_t*)(ol_out + base0 + nh*8) = lp;
        split2h(gv1.x*y1[nh][0]*s1, gv1.y*y1[nh][1]*s1, hp, lp);
        *(uint32_t*)(oh_out + base1 + nh*8) = hp;
        *(uint32_t*)(ol_out + base1 + nh*8) = lp;
    }
}

// ---------------- final RMS norm over D, scaled by 1/sqrt(48) ----------------
__global__ void final_norm_kernel(const float* __restrict__ in, float* __restrict__ out)
{
    __shared__ float sbuf[8];
    const int tok = blockIdx.x;
    const float* p = in + (size_t)tok*D_;
    const int base = threadIdx.x * 8;

    float4 a = *(const float4*)(p + base);
    float4 b = *(const float4*)(p + base + 4);
    float ss = a.x*a.x + a.y*a.y + a.z*a.z + a.w*a.w
             + b.x*b.x + b.y*b.y + b.z*b.z + b.w*b.w;
#pragma unroll
    for (int o = 16; o > 0; o >>= 1) ss += __shfl_xor_sync(0xffffffffu, ss, o);
    if ((threadIdx.x & 31) == 0) sbuf[threadIdx.x >> 5] = ss;
    __syncthreads();
    float tot = 0.f;
#pragma unroll
    for (int i = 0; i < 8; i++) tot += sbuf[i];
    float r = rsqrtf(tot * (1.f/D_) + 1e-8f) * 0.14433756729740643f;

    float* q = out + (size_t)tok*D_;
    a.x*=r; a.y*=r; a.z*=r; a.w*=r;
    b.x*=r; b.y*=r; b.z*=r; b.w*=r;
    *(float4*)(q + base)     = a;
    *(float4*)(q + base + 4) = b;
}

// ---------------- launcher ----------------
extern "C" void kernel_launch(void* const* d_in, const int* in_sizes, int n_in,
                              void* d_out, int out_size)
{
    (void)in_sizes; (void)n_in; (void)out_size;
    const float* xq = (const float*)d_in[0];
    const float* xk = (const float*)d_in[1];
    const float* xv = (const float*)d_in[2];
    const float* Wq = (const float*)d_in[3];
    const float* Wk = (const float*)d_in[4];
    const float* Wv = (const float*)d_in[5];
    const float* Wg = (const float*)d_in[6];
    const float* Wo = (const float*)d_in[7];
    const float* mk = (const float*)d_in[8];
    const float* mv = (const float*)d_in[9];
    float* out = (float*)d_out;

    float *pq, *pk, *pv, *pg, *po;
    __half *pah, *pal, *pakh, *pakl, *pavh, *pavl, *pwth;
    __half *pwkh, *pwvh;
    __half *pqh, *pql, *pkh, *pvh;
    cudaGetSymbolAddress((void**)&pq,   g_q);
    cudaGetSymbolAddress((void**)&pk,   g_k);
    cudaGetSymbolAddress((void**)&pv,   g_v);
    cudaGetSymbolAddress((void**)&pg,   g_g);
    cudaGetSymbolAddress((void**)&po,   g_o);
    cudaGetSymbolAddress((void**)&pah,  g_ah);
    cudaGetSymbolAddress((void**)&pal,  g_al);
    cudaGetSymbolAddress((void**)&pakh, g_akh);
    cudaGetSymbolAddress((void**)&pakl, g_akl);
    cudaGetSymbolAddress((void**)&pavh, g_avh);
    cudaGetSymbolAddress((void**)&pavl, g_avl);
    cudaGetSymbolAddress((void**)&pwth, g_wth);
    cudaGetSymbolAddress((void**)&pwkh, g_wkth);
    cudaGetSymbolAddress((void**)&pwvh, g_wvth);
    cudaGetSymbolAddress((void**)&pqh,  g_qh);
    cudaGetSymbolAddress((void**)&pql,  g_ql);
    cudaGetSymbolAddress((void**)&pkh,  g_kh);
    cudaGetSymbolAddress((void**)&pvh,  g_vh);

    cudaFuncSetAttribute(gemm_mma_big, cudaFuncAttributeMaxDynamicSharedMemorySize,
                         BG_SMEM);
    cudaFuncSetAttribute(gemm_mma_qkv, cudaFuncAttributeMaxDynamicSharedMemorySize,
                         BG_SMEM);
    cudaFuncSetAttribute(flash_mma_kernel, cudaFuncAttributeMaxDynamicSharedMemorySize,
                         FLASH_SMEM);

    const int XS_GRID = (NTOK*D_/4)/256;
    dim3 wgrid_full(D_/32, D_/128), wgrid_kv(512/32, D_/128), wblk(32, 32);

    // 1) fused mix/split (xq, xk, xv) + weight transposes (single fp16)
    mix_split_kernel<<<XS_GRID, 256>>>(xq, xk, xv, mk, mv,
                                       pah, pal, pakh, pakl, pavh, pavl);
    wsplit_t_kernel<<<wgrid_full, wblk>>>(Wq, pwth, D_);
    wsplit_t_kernel<<<wgrid_full, wblk>>>(Wg, pwth + (size_t)D_*D_, D_);
    wsplit_t_kernel<<<wgrid_kv, wblk>>>(Wk, pwkh, 512);
    wsplit_t_kernel<<<wgrid_kv, wblk>>>(Wv, pwvh, 512);

    // 2) fused q/k/v/g projections: single 640-tile launch
    gemm_mma_qkv<<<QKV_TILES, 256, BG_SMEM>>>(
        pah, pal, pakh, pakl, pavh, pavl,
        pwth, pwkh, pwvh,
        pq, pg, pk, pv);

    // 3) fused per-head RMS norm (+RoPE): q split, k/v single
    norm_all_kernel<<<NQBLK + 2*NKBLK, 128>>>(pq, pk, pv,
                                              pqh, pql, pkh, pvh);

    // 4) causal GQA attention + fused L2-norm/gate/split epilogue
    flash_mma_kernel<<<dim3(T_/128, B_*H_), 256, FLASH_SMEM>>>(
        pqh, pql, pkh, pvh, pg, pah, pal);

    // 5) output projection
    wsplit_t_kernel<<<wgrid_full, wblk>>>(Wo, pwth, D_);
    gemm_mma_big<<<dim3(D_/128, NTOK/256), 256, BG_SMEM>>>(
        pah, pal, pwth, po, nullptr, D_);

    // 6) final RMS norm + 1/sqrt(2*N_LAYER)
    final_norm_kernel<<<NTOK, 256>>>(po, out);
}

// round 14
// speedup vs baseline: 1.4424x; 1.0878x over previous
#include <cuda_runtime.h>
#include <cuda_fp16.h>
#include <math.h>
#include <stdint.h>

#define B_    2
#define T_    2048
#define D_    2048
#define H_    16
#define KVH_  4
#define HD_   128
#define NTOK  (B_*T_)

// ---------------- scratch (device globals: allocation-free) ----------------
__device__ float g_q  [NTOK*D_];
__device__ float g_k  [NTOK*KVH_*HD_];
__device__ float g_v  [NTOK*KVH_*HD_];
__device__ float g_g  [NTOK*D_];
__device__ float g_o  [NTOK*D_];
// split-fp16 A-side operands (hi+lo), single-fp16 B-side (weights)
__device__ __align__(16) __half g_ah [NTOK*D_];
__device__ __align__(16) __half g_al [NTOK*D_];
__device__ __align__(16) __half g_akh[NTOK*D_];
__device__ __align__(16) __half g_akl[NTOK*D_];
__device__ __align__(16) __half g_avh[NTOK*D_];
__device__ __align__(16) __half g_avl[NTOK*D_];
__device__ __align__(16) __half g_wth [3*D_*D_];     /* Wq | Wg | Wo */
__device__ __align__(16) __half g_wkth[512*D_];
__device__ __align__(16) __half g_wvth[512*D_];
// attention operands (all single fp16 except P which is split on the fly)
__device__ __align__(16) __half g_qh [NTOK*D_];
__device__ __align__(16) __half g_kh [NTOK*KVH_*HD_];
__device__ __align__(16) __half g_vh [NTOK*KVH_*HD_];
// RoPE table: [t][j] -> (cos, sin)
__device__ __align__(16) float2 g_rope[T_*64];

// ================= baseline-ISA helpers =================
__device__ __forceinline__ uint32_t smem_u32(const void* p) {
    uint32_t a;
    asm("{ .reg .u64 t; cvta.to.shared.u64 t, %1; cvt.u32.u64 %0, t; }" : "=r"(a) : "l"(p));
    return a;
}
__device__ __forceinline__ uint32_t sw128(uint32_t off) { return off ^ ((off >> 3) & 0x70); }
__device__ __forceinline__ uint32_t sw256(uint32_t off) { return off ^ ((off >> 4) & 0x70); }

__device__ __forceinline__ void cp_async16(uint32_t dst, const void* src) {
    asm volatile("cp.async.cg.shared.global [%0], [%1], 16;" :: "r"(dst), "l"(src) : "memory");
}
#define CP_COMMIT() asm volatile("cp.async.commit_group;" ::: "memory")
#define CP_WAIT(n)  asm volatile("cp.async.wait_group %0;" :: "n"(n) : "memory")

__device__ __forceinline__ void ldsm_x4(uint32_t* r, uint32_t addr) {
    asm volatile("ldmatrix.sync.aligned.m8n8.x4.shared.b16 {%0,%1,%2,%3}, [%4];"
                 : "=r"(r[0]), "=r"(r[1]), "=r"(r[2]), "=r"(r[3]) : "r"(addr));
}
__device__ __forceinline__ void ldsm_x4_t(uint32_t* r, uint32_t addr) {
    asm volatile("ldmatrix.sync.aligned.m8n8.x4.trans.shared.b16 {%0,%1,%2,%3}, [%4];"
                 : "=r"(r[0]), "=r"(r[1]), "=r"(r[2]), "=r"(r[3]) : "r"(addr));
}
__device__ __forceinline__ void mma16816(float* d, const uint32_t* a, const uint32_t* b) {
    asm volatile("mma.sync.aligned.m16n8k16.row.col.f32.f16.f16.f32 "
                 "{%0,%1,%2,%3}, {%4,%5,%6,%7}, {%8,%9}, {%0,%1,%2,%3};"
                 : "+f"(d[0]), "+f"(d[1]), "+f"(d[2]), "+f"(d[3])
                 : "r"(a[0]), "r"(a[1]), "r"(a[2]), "r"(a[3]), "r"(b[0]), "r"(b[1]));
}

// fast exp on the FMA pipe
__device__ __forceinline__ float fast_exp(float x) {
    x = fmaxf(x, -80.f);
    const float LOG2E = 1.4426950408889634f;
    float t = x * LOG2E;
    float r = t + 12582912.f;
    float i = r - 12582912.f;
    float f = t - i;
    uint32_t ib = __float_as_uint(r);
    float sc = __uint_as_float((ib + 127u) << 23);
    float p = 1.3333558146e-3f;
    p = fmaf(p, f, 9.6181291076e-3f);
    p = fmaf(p, f, 5.5504108664e-2f);
    p = fmaf(p, f, 2.4022650696e-1f);
    p = fmaf(p, f, 6.9314718056e-1f);
    p = fmaf(p, f, 1.0f);
    return p * sc;
}

__device__ __forceinline__ void split2h(float a, float b, uint32_t& hp, uint32_t& lp) {
    __half ha = __float2half_rn(a), hb = __float2half_rn(b);
    __half la = __float2half_rn(a - __half2float(ha));
    __half lb = __float2half_rn(b - __half2float(hb));
    hp = ((uint32_t)__half_as_ushort(hb) << 16) | __half_as_ushort(ha);
    lp = ((uint32_t)__half_as_ushort(lb) << 16) | __half_as_ushort(la);
}
__device__ __forceinline__ uint32_t pack2h(float a, float b) {
    __half ha = __float2half_rn(a), hb = __float2half_rn(b);
    return ((uint32_t)__half_as_ushort(hb) << 16) | __half_as_ushort(ha);
}

// ================= elementwise kernels =================
// RoPE cos/sin table fill: idx = t*64 + j
__global__ void rope_fill_kernel(float2* __restrict__ tab)
{
    int idx = blockIdx.x * blockDim.x + threadIdx.x;
    int t = idx >> 6, j = idx & 63;
    float inv_freq = exp2f(-(float)j * (13.287712379549449f / 64.f));
    float ang = (float)t * inv_freq;
    float sn, cs;
    sincosf(ang, &sn, &cs);
    tab[idx] = make_float2(cs, sn);
}

// fused: xq split + time-shift mix + split for k/v paths
__global__ void mix_split_kernel(const float* __restrict__ xq,
                                 const float* __restrict__ xk, const float* __restrict__ xv,
                                 const float* __restrict__ mk, const float* __restrict__ mv,
                                 __half* __restrict__ qh2, __half* __restrict__ ql2,
                                 __half* __restrict__ kh, __half* __restrict__ kl,
                                 __half* __restrict__ vh, __half* __restrict__ vl)
{
    const int D4 = D_ / 4;
    int idx = blockIdx.x * blockDim.x + threadIdx.x;
    int d4  = idx & (D4 - 1);
    int tok = idx >> 9;
    int t   = tok & (T_ - 1);

    {
        float4 v = ((const float4*)xq)[idx];
        uint32_t h0, l0, h1, l1;
        split2h(v.x, v.y, h0, l0);
        split2h(v.z, v.w, h1, l1);
        ((uint2*)qh2)[idx] = make_uint2(h0, h1);
        ((uint2*)ql2)[idx] = make_uint2(l0, l1);
    }

    float4 kc = ((const float4*)xk)[idx];
    float4 vc = ((const float4*)xv)[idx];
    float4 m1 = ((const float4*)mk)[d4];
    float4 m2 = ((const float4*)mv)[d4];
    float4 kp = make_float4(0.f,0.f,0.f,0.f);
    float4 vp = make_float4(0.f,0.f,0.f,0.f);
    if (t > 0) {
        kp = ((const float4*)xk)[idx - D4];
        vp = ((const float4*)xv)[idx - D4];
    }
    float4 r1, r2;
    r1.x = kc.x + m1.x*(kp.x-kc.x);  r1.y = kc.y + m1.y*(kp.y-kc.y);
    r1.z = kc.z + m1.z*(kp.z-kc.z);  r1.w = kc.w + m1.w*(kp.w-kc.w);
    r2.x = vc.x + m2.x*(vp.x-vc.x);  r2.y = vc.y + m2.y*(vp.y-vc.y);
    r2.z = vc.z + m2.z*(vp.z-vc.z);  r2.w = vc.w + m2.w*(vp.w-vc.w);

    uint32_t h0, l0, h1, l1;
    split2h(r1.x, r1.y, h0, l0);  split2h(r1.z, r1.w, h1, l1);
    ((uint2*)kh)[idx] = make_uint2(h0, h1);
    ((uint2*)kl)[idx] = make_uint2(l0, l1);
    split2h(r2.x, r2.y, h0, l0);  split2h(r2.z, r2.w, h1, l1);
    ((uint2*)vh)[idx] = make_uint2(h0, h1);
    ((uint2*)vl)[idx] = make_uint2(l0, l1);
}

// ---- merged weight transpose: all 5 weights in one flat-grid launch ----
__device__ __forceinline__ void wsplit_body(const float* __restrict__ W,
                                            __half* __restrict__ th, int N,
                                            int bx, int by)
{
    __shared__ float s[32][132];
    const int k0 = by * 128, n0 = bx * 32;
    const int tx = threadIdx.x, ty = threadIdx.y;
    const int tid = ty * 32 + tx;

#pragma unroll
    for (int i = 0; i < 4; i++) {
        int kk = ty + 32*i;
        s[tx][kk] = W[(size_t)(k0 + kk) * N + n0 + tx];
    }
    __syncthreads();

    const int r = tid >> 5, seg = tid & 31;
    float4 v = *(const float4*)(&s[r][seg << 2]);
    uint32_t h0 = pack2h(v.x, v.y);
    uint32_t h1 = pack2h(v.z, v.w);
    size_t o = ((size_t)(n0 + r) * D_ + k0 + (seg << 2)) >> 2;
    ((uint2*)th)[o] = make_uint2(h0, h1);
}

// grid: 1024 (Wq) + 1024 (Wg) + 256 (Wk) + 256 (Wv) + 1024 (Wo) = 3584
__global__ void wsplit_all_kernel(const float* __restrict__ Wq, const float* __restrict__ Wg,
                                  const float* __restrict__ Wk, const float* __restrict__ Wv,
                                  const float* __restrict__ Wo,
                                  __half* __restrict__ wqg_o, __half* __restrict__ wk,
                                  __half* __restrict__ wv)
{
    const int idx = blockIdx.x;
    if (idx < 1024) {
        wsplit_body(Wq, wqg_o, D_, idx & 63, idx >> 6);
    } else if (idx < 2048) {
        const int i = idx - 1024;
        wsplit_body(Wg, wqg_o + (size_t)D_*D_, D_, i & 63, i >> 6);
    } else if (idx < 2304) {
        const int i = idx - 2048;
        wsplit_body(Wk, wk, 512, i & 15, i >> 4);
    } else if (idx < 2560) {
        const int i = idx - 2304;
        wsplit_body(Wv, wv, 512, i & 15, i >> 4);
    } else {
        const int i = idx - 2560;
        wsplit_body(Wo, wqg_o + (size_t)2*D_*D_, D_, i & 63, i >> 6);
    }
}

#define GK  2048
#define NCH (GK/64)

// ================= BIG GEMM body: 256x128 block, 64x64 warps, 2-term fp16 ==
#define BG_A     32768
#define BG_B     16384
#define BG_STAGE (2*BG_A + BG_B)
#define BG_SMEM  (2*BG_STAGE + 1024)

__device__ __forceinline__ void gemm_big_body(
    const __half* __restrict__ ah, const __half* __restrict__ al,
    const __half* __restrict__ wth,
    float* __restrict__ C0, float* __restrict__ C1, int cstride,
    int m0, int n0, char* sm)
{
    const uint32_t smb   = smem_u32(sm);
    const uint32_t tiles = (smb + 1023u) & ~1023u;

    const int tid  = threadIdx.x;
    const int wid  = tid >> 5, lane = tid & 31;
    const int wm   = wid & 3,  wn   = wid >> 2;

    const __half* pAh = ah  + (size_t)m0 * GK;
    const __half* pAl = al  + (size_t)m0 * GK;
    const __half* pB  = wth + (size_t)n0 * GK;

    float acc[4][8][4];
#pragma unroll
    for (int i = 0; i < 4; i++)
#pragma unroll
        for (int j = 0; j < 8; j++)
#pragma unroll
            for (int q = 0; q < 4; q++) acc[i][j][q] = 0.f;

    auto prefetch = [&](int ch) {
        const uint32_t stage = tiles + (uint32_t)(ch & 1) * BG_STAGE;
        const int ke = ch << 6;
#pragma unroll
        for (int j = 0; j < 8; j++) {
            int idx = tid + (j << 8);
            int r = idx >> 3, c = idx & 7;
            uint32_t off = sw128((r << 7) + (c << 4));
            const size_t go = (size_t)r * GK + ke + (c << 3);
            cp_async16(stage + off,        pAh + go);
            cp_async16(stage + BG_A + off, pAl + go);
        }
#pragma unroll
        for (int j = 0; j < 4; j++) {
            int idx = tid + (j << 8);
            int r = idx >> 3, c = idx & 7;
            uint32_t off = sw128((r << 7) + (c << 4));
            cp_async16(stage + 2*BG_A + off, pB + (size_t)r * GK + ke + (c << 3));
        }
        CP_COMMIT();
    };

    prefetch(0);

    for (int ch = 0; ch < NCH; ch++) {
        if (ch + 1 < NCH) { prefetch(ch + 1); CP_WAIT(1); }
        else              { CP_WAIT(0); }
        __syncthreads();

        const uint32_t stage = tiles + (uint32_t)(ch & 1) * BG_STAGE;
        const uint32_t sAh = stage, sAl = stage + BG_A, sB = stage + 2*BG_A;

#pragma unroll
        for (int ks = 0; ks < 4; ks++) {
            const int kb = ks << 5;

            uint32_t ahf[4][4], alf[4][4];
#pragma unroll
            for (int mt = 0; mt < 4; mt++) {
                int row = wm*64 + mt*16 + (lane & 15);
                uint32_t off = sw128((uint32_t)(row << 7) + kb + ((lane >> 4) << 4));
                ldsm_x4(ahf[mt], sAh + off);
                ldsm_x4(alf[mt], sAl + off);
            }
            const int brow = wn*64 + (lane & 7) + ((lane >> 4) << 3);
            const int bko  = kb + (((lane >> 3) & 1) << 4);
#pragma unroll
            for (int np = 0; np < 4; np++) {
                uint32_t bh[4];
                uint32_t off = sw128((uint32_t)((brow + np*16) << 7) + bko);
                ldsm_x4(bh, sB + off);
#pragma unroll
                for (int mt = 0; mt < 4; mt++) {
                    mma16816(acc[mt][2*np],   ahf[mt], bh);
                    mma16816(acc[mt][2*np+1], ahf[mt], bh + 2);
                }
#pragma unroll
                for (int mt = 0; mt < 4; mt++) {
                    mma16816(acc[mt][2*np],   alf[mt], bh);
                    mma16816(acc[mt][2*np+1], alf[mt], bh + 2);
                }
            }
        }
        __syncthreads();
    }

    float* C = C0;
    int nc = n0;
    if (C1 != nullptr && n0 >= cstride) { C = C1; nc = n0 - cstride; }

    const int er = lane >> 2, ec = (lane & 3) << 1;
#pragma unroll
    for (int mt = 0; mt < 4; mt++) {
        int r0 = m0 + wm*64 + mt*16 + er;
#pragma unroll
        for (int nt = 0; nt < 8; nt++) {
            int c = nc + wn*64 + nt*8 + ec;
            *(float2*)(C + (size_t)r0      * cstride + c) = make_float2(acc[mt][nt][0], acc[mt][nt][1]);
            *(float2*)(C + (size_t)(r0 + 8)* cstride + c) = make_float2(acc[mt][nt][2], acc[mt][nt][3]);
        }
    }
}

__global__ void __launch_bounds__(256, 1) gemm_mma_big(
    const __half* __restrict__ ah, const __half* __restrict__ al,
    const __half* __restrict__ wth,
    float* __restrict__ C0, float* __restrict__ C1, int cstride)
{
    extern __shared__ char sm[];
    gemm_big_body(ah, al, wth, C0, C1, cstride,
                  blockIdx.y << 8, blockIdx.x << 7, sm);
}

#define QKV_TILES 640
__global__ void __launch_bounds__(256, 1) gemm_mma_qkv(
    const __half* __restrict__ aqh, const __half* __restrict__ aql,
    const __half* __restrict__ akh, const __half* __restrict__ akl,
    const __half* __restrict__ avh, const __half* __restrict__ avl,
    const __half* __restrict__ wqh, const __half* __restrict__ wkh,
    const __half* __restrict__ wvh,
    float* __restrict__ pq, float* __restrict__ pg,
    float* __restrict__ pk, float* __restrict__ pv)
{
    extern __shared__ char sm[];
    const int idx = blockIdx.x;
    if (idx < 512) {
        gemm_big_body(aqh, aql, wqh, pq, pg, D_,
                      (idx >> 5) << 8, (idx & 31) << 7, sm);
    } else if (idx < 576) {
        const int i = idx - 512;
        gemm_big_body(akh, akl, wkh, pk, nullptr, 512,
                      (i >> 2) << 8, (i & 3) << 7, sm);
    } else {
        const int i = idx - 576;
        gemm_big_body(avh, avl, wvh, pv, nullptr, 512,
                      (i >> 2) << 8, (i & 3) << 7, sm);
    }
}

// ---- fused per-head RMS norm (+RoPE via table), single fp16 output ----
__device__ __forceinline__ void norm_head_body(
    const float* __restrict__ x, int heads, int do_rope, float scale,
    const float2* __restrict__ rope,
    __half* __restrict__ oh, int blk)
{
    __shared__ float sbuf[4];
    __shared__ float svals[128];
    const int head = blk % heads;
    const int tok  = blk / heads;
    const int t    = tok % T_;
    const size_t base = (size_t)tok*heads*HD_ + head*HD_;
    const float* p = x + base;
    const int d = threadIdx.x;

    float v  = p[d];
    float ss = v*v;
#pragma unroll
    for (int o = 16; o > 0; o >>= 1) ss += __shfl_xor_sync(0xffffffffu, ss, o);
    if ((d & 31) == 0) sbuf[d >> 5] = ss;
    __syncthreads();
    float tot = sbuf[0] + sbuf[1] + sbuf[2] + sbuf[3];
    float r   = rsqrtf(tot * (1.f/HD_) + 1e-8f);
    float vn  = v * r;
    float f;

    if (do_rope) {
        svals[d] = vn;
        __syncthreads();
        int   j  = d & 63;
        float2 cs = rope[t*64 + j];
        float partner = svals[d ^ 64];
        f = (d < 64) ? (vn*cs.x - partner*cs.y) : (vn*cs.x + partner*cs.y);
    } else {
        f = vn;
    }
    f *= scale;
    oh[base + d] = __float2half_rn(f);
}

#define NQBLK (NTOK*H_)
#define NKBLK (NTOK*KVH_)
__global__ void norm_all_kernel(
    const float* __restrict__ pq, const float* __restrict__ pk, const float* __restrict__ pv,
    const float2* __restrict__ rope,
    __half* __restrict__ qh, __half* __restrict__ kh, __half* __restrict__ vh)
{
    const int blk = blockIdx.x;
    if (blk < NQBLK) {
        norm_head_body(pq, H_, 1, 0.08838834764831845f, rope, qh, blk);
    } else if (blk < NQBLK + NKBLK) {
        norm_head_body(pk, KVH_, 1, 1.f, rope, kh, blk - NQBLK);
    } else {
        norm_head_body(pv, KVH_, 0, 1.f, rope, vh, blk - NQBLK - NKBLK);
    }
}

// ================= flash attention: Q/K/V single fp16, P split =============
#define FQH  0
#define FKV  32768
#define FSTG 32768
#define FLASH_SMEM (FKV + 2*FSTG)

__global__ void __launch_bounds__(256, 1) flash_mma_kernel(
    const __half* __restrict__ qh,
    const __half* __restrict__ kh, const __half* __restrict__ vh,
    const float* __restrict__ g,
    __half* __restrict__ oh_out, __half* __restrict__ ol_out)
{
    extern __shared__ char sm[];
    const uint32_t smb = smem_u32(sm);

    const int tid  = threadIdx.x;
    const int w    = tid >> 5, lane = tid & 31;
    const int qt   = (gridDim.x - 1) - blockIdx.x;
    const int b    = blockIdx.y >> 4;
    const int h    = blockIdx.y & 15;
    const int kvh  = h >> 2;
    const int qs   = qt << 7;

    // ---- async load Q tile (group 0) ----
    {
        const __half* qg = qh + ((size_t)(b*T_ + qs))*D_ + h*HD_;
#pragma unroll
        for (int it = 0; it < 8; it++) {
            int idx = tid + (it << 8);
            int r = idx >> 4, c = idx & 15;
            cp_async16(smb + FQH + sw256((r << 8) + (c << 4)),
                       qg + (size_t)r*D_ + (c << 3));
        }
        CP_COMMIT();
    }

    const __half* kh_b = kh + (size_t)(b*T_)*(KVH_*HD_) + kvh*HD_;
    const __half* vh_b = vh + (size_t)(b*T_)*(KVH_*HD_) + kvh*HD_;

    auto prefetch_kv = [&](int kt) {
        const uint32_t sb = smb + FKV + (uint32_t)(kt & 1)*FSTG;
        const size_t rb = (size_t)(kt << 6) * (KVH_*HD_);
        const __half* ps[2] = { kh_b + rb, vh_b + rb };
#pragma unroll
        for (int t = 0; t < 2; t++) {
#pragma unroll
            for (int it = 0; it < 4; it++) {
                int idx = tid + (it << 8);
                int r = idx >> 4, c = idx & 15;
                cp_async16(sb + t*16384 + sw256((r << 8) + (c << 4)),
                           ps[t] + (size_t)r*(KVH_*HD_) + (c << 3));
            }
        }
        CP_COMMIT();
    };

    prefetch_kv(0);

    // ---- hoist Q fragments ----
    uint32_t aQh[8][4];
    CP_WAIT(1);
    __syncthreads();
#pragma unroll
    for (int ks8 = 0; ks8 < 8; ks8++) {
        int row = (w << 4) + (lane & 15);
        uint32_t off = sw256((uint32_t)(row << 8) + (ks8 << 5) + ((lane >> 4) << 4));
        ldsm_x4(aQh[ks8], smb + FQH + off);
    }

    float o[16][4];
#pragma unroll
    for (int nh = 0; nh < 16; nh++)
#pragma unroll
        for (int qq = 0; qq < 4; qq++) o[nh][qq] = 0.f;
    float m0 = -1e30f, m1 = -1e30f, l0 = 0.f, l1 = 0.f;

    const int nkv = 2*qt + 2;
    for (int kt = 0; kt < nkv; kt++) {
        const int ks = kt << 6;
        if (kt + 1 < nkv) { prefetch_kv(kt + 1); CP_WAIT(1); }
        else              { CP_WAIT(0); }
        __syncthreads();

        const uint32_t sb  = smb + FKV + (uint32_t)(kt & 1)*FSTG;
        const uint32_t sKH = sb, sVH = sb + 16384;

        // ---- S = Q K^T (single pass) ----
        float s[8][4];
#pragma unroll
        for (int nt = 0; nt < 8; nt++)
#pragma unroll
            for (int qq = 0; qq < 4; qq++) s[nt][qq] = 0.f;

#pragma unroll
        for (int ks8 = 0; ks8 < 8; ks8++) {
            const int kb = ks8 << 5;
            uint32_t bhf[4][4];
            const int brow4 = (lane & 7) + ((lane >> 4) << 3);
            const int bko   = kb + (((lane >> 3) & 1) << 4);
#pragma unroll
            for (int np = 0; np < 4; np++) {
                uint32_t off = sw256((uint32_t)((brow4 + np*16) << 8) + bko);
                ldsm_x4(bhf[np], sKH + off);
            }
#pragma unroll
            for (int np = 0; np < 4; np++) {
                mma16816(s[2*np],   aQh[ks8], bhf[np]);
                mma16816(s[2*np+1], aQh[ks8], bhf[np] + 2);
            }
        }

        // ---- causal mask ----
        if (kt >= 2*qt) {
            const int gr0 = qs + (w << 4) + (lane >> 2);
            const int gc0 = ks + ((lane & 3) << 1);
#pragma unroll
            for (int nt = 0; nt < 8; nt++) {
                int c = gc0 + nt*8;
                if (c     > gr0)     s[nt][0] = -1e30f;
                if (c + 1 > gr0)     s[nt][1] = -1e30f;
                if (c     > gr0 + 8) s[nt][2] = -1e30f;
                if (c + 1 > gr0 + 8) s[nt][3] = -1e30f;
            }
        }

        // ---- online softmax ----
        float mx0 = -1e30f, mx1 = -1e30f;
#pragma unroll
        for (int nt = 0; nt < 8; nt++) {
            mx0 = fmaxf(mx0, fmaxf(s[nt][0], s[nt][1]));
            mx1 = fmaxf(mx1, fmaxf(s[nt][2], s[nt][3]));
        }
        mx0 = fmaxf(mx0, __shfl_xor_sync(0xffffffffu, mx0, 1));
        mx0 = fmaxf(mx0, __shfl_xor_sync(0xffffffffu, mx0, 2));
        mx1 = fmaxf(mx1, __shfl_xor_sync(0xffffffffu, mx1, 1));
        mx1 = fmaxf(mx1, __shfl_xor_sync(0xffffffffu, mx1, 2));
        float m0n = fmaxf(m0, mx0), m1n = fmaxf(m1, mx1);
        float sc0 = fast_exp(m0 - m0n), sc1 = fast_exp(m1 - m1n);
        m0 = m0n; m1 = m1n;

        float sum0 = 0.f, sum1 = 0.f;
#pragma unroll
        for (int nt = 0; nt < 8; nt++) {
            s[nt][0] = fast_exp(s[nt][0] - m0n); sum0 += s[nt][0];
            s[nt][1] = fast_exp(s[nt][1] - m0n); sum0 += s[nt][1];
            s[nt][2] = fast_exp(s[nt][2] - m1n); sum1 += s[nt][2];
            s[nt][3] = fast_exp(s[nt][3] - m1n); sum1 += s[nt][3];
        }
        sum0 += __shfl_xor_sync(0xffffffffu, sum0, 1);
        sum0 += __shfl_xor_sync(0xffffffffu, sum0, 2);
        sum1 += __shfl_xor_sync(0xffffffffu, sum1, 1);
        sum1 += __shfl_xor_sync(0xffffffffu, sum1, 2);
        l0 = l0*sc0 + sum0;
        l1 = l1*sc1 + sum1;

#pragma unroll
        for (int nh = 0; nh < 16; nh++) {
            o[nh][0] *= sc0; o[nh][1] *= sc0;
            o[nh][2] *= sc1; o[nh][3] *= sc1;
        }

        // ---- O += P V (P split, V single) ----
#pragma unroll
        for (int j = 0; j < 4; j++) {
            uint32_t aPh[4], aPl[4];
            split2h(s[2*j][0],   s[2*j][1],   aPh[0], aPl[0]);
            split2h(s[2*j][2],   s[2*j][3],   aPh[1], aPl[1]);
            split2h(s[2*j+1][0], s[2*j+1][1], aPh[2], aPl[2]);
            split2h(s[2*j+1][2], s[2*j+1][3], aPh[3], aPl[3]);
            const uint32_t vrow = (j << 4) + (lane & 15);
            const uint32_t nsel = (lane >> 4);
#pragma unroll
            for (int pp = 0; pp < 4; pp++) {
                uint32_t bh0[4], bh1[4];
                uint32_t off0 = sw256((vrow << 8) + ((4*pp     + nsel) << 4));
                uint32_t off1 = sw256((vrow << 8) + ((4*pp + 2 + nsel) << 4));
                ldsm_x4_t(bh0, sVH + off0);
                ldsm_x4_t(bh1, sVH + off1);
                mma16816(o[4*pp],   aPh, bh0);
                mma16816(o[4*pp+1], aPh, bh0 + 2);
                mma16816(o[4*pp+2], aPh, bh1);
                mma16816(o[4*pp+3], aPh, bh1 + 2);
                mma16816(o[4*pp],   aPl, bh0);
                mma16816(o[4*pp+1], aPl, bh0 + 2);
                mma16816(o[4*pp+2], aPl, bh1);
                mma16816(o[4*pp+3], aPl, bh1 + 2);
            }
        }
        __syncthreads();
    }

    // ---- fused epilogue: 1/l, per-head L2 norm, gate, split-fp16 out ----
    const float inv0 = 1.f / l0, inv1 = 1.f / l1;
    float y0[16][2], y1[16][2];
    float ss0 = 0.f, ss1 = 0.f;
#pragma unroll
    for (int nh = 0; nh < 16; nh++) {
        y0[nh][0] = o[nh][0]*inv0;  y0[nh][1] = o[nh][1]*inv0;
        y1[nh][0] = o[nh][2]*inv1;  y1[nh][1] = o[nh][3]*inv1;
        ss0 += y0[nh][0]*y0[nh][0] + y0[nh][1]*y0[nh][1];
        ss1 += y1[nh][0]*y1[nh][0] + y1[nh][1]*y1[nh][1];
    }
    ss0 += __shfl_xor_sync(0xffffffffu, ss0, 1);
    ss0 += __shfl_xor_sync(0xffffffffu, ss0, 2);
    ss1 += __shfl_xor_sync(0xffffffffu, ss1, 1);
    ss1 += __shfl_xor_sync(0xffffffffu, ss1, 2);
    const float s0 = 1.f / fmaxf(sqrtf(ss0), 1e-12f);
    const float s1 = 1.f / fmaxf(sqrtf(ss1), 1e-12f);

    const int r0 = qs + (w << 4) + (lane >> 2);
    const size_t base0 = ((size_t)(b*T_) + r0)*D_ + h*HD_ + ((lane & 3) << 1);
    const size_t base1 = base0 + (size_t)8*D_;
#pragma unroll
    for (int nh = 0; nh < 16; nh++) {
        float2 gv0 = *(const float2*)(g + base0 + nh*8);
        float2 gv1 = *(const float2*)(g + base1 + nh*8);
        uint32_t hp, lp;
        split2h(gv0.x*y0[nh][0]*s0, gv0.y*y0[nh][1]*s0, hp, lp);
        *(uint32_t*)(oh_out + base0 + nh*8) = hp;
        *(uint32_t*)(ol_out + base0 + nh*8) = lp;
        split2h(gv1.x*y1[nh][0]*s1, gv1.y*y1[nh][1]*s1, hp, lp);
        *(uint32_t*)(oh_out + base1 + nh*8) = hp;
        *(uint32_t*)(ol_out + base1 + nh*8) = lp;
    }
}

// ---------------- final RMS norm over D, scaled by 1/sqrt(48) ----------------
__global__ void final_norm_kernel(const float* __restrict__ in, float* __restrict__ out)
{
    __shared__ float sbuf[8];
    const int tok = blockIdx.x;
    const float* p = in + (size_t)tok*D_;
    const int base = threadIdx.x * 8;

    float4 a = *(const float4*)(p + base);
    float4 b = *(const float4*)(p + base + 4);
    float ss = a.x*a.x + a.y*a.y + a.z*a.z + a.w*a.w
             + b.x*b.x + b.y*b.y + b.z*b.z + b.w*b.w;
#pragma unroll
    for (int o = 16; o > 0; o >>= 1) ss += __shfl_xor_sync(0xffffffffu, ss, o);
    if ((threadIdx.x & 31) == 0) sbuf[threadIdx.x >> 5] = ss;
    __syncthreads();
    float tot = 0.f;
#pragma unroll
    for (int i = 0; i < 8; i++) tot += sbuf[i];
    float r = rsqrtf(tot * (1.f/D_) + 1e-8f) * 0.14433756729740643f;

    float* q = out + (size_t)tok*D_;
    a.x*=r; a.y*=r; a.z*=r; a.w*=r;
    b.x*=r; b.y*=r; b.z*=r; b.w*=r;
    *(float4*)(q + base)     = a;
    *(float4*)(q + base + 4) = b;
}

// ---------------- launcher ----------------
extern "C" void kernel_launch(void* const* d_in, const int* in_sizes, int n_in,
                              void* d_out, int out_size)
{
    (void)in_sizes; (void)n_in; (void)out_size;
    const float* xq = (const float*)d_in[0];
    const float* xk = (const float*)d_in[1];
    const float* xv = (const float*)d_in[2];
    const float* Wq = (const float*)d_in[3];
    const float* Wk = (const float*)d_in[4];
    const float* Wv = (const float*)d_in[5];
    const float* Wg = (const float*)d_in[6];
    const float* Wo = (const float*)d_in[7];
    const float* mk = (const float*)d_in[8];
    const float* mv = (const float*)d_in[9];
    float* out = (float*)d_out;

    float *pq, *pk, *pv, *pg, *po;
    __half *pah, *pal, *pakh, *pakl, *pavh, *pavl, *pwth;
    __half *pwkh, *pwvh;
    __half *pqh, *pkh, *pvh;
    float2* prope;
    cudaGetSymbolAddress((void**)&pq,   g_q);
    cudaGetSymbolAddress((void**)&pk,   g_k);
    cudaGetSymbolAddress((void**)&pv,   g_v);
    cudaGetSymbolAddress((void**)&pg,   g_g);
    cudaGetSymbolAddress((void**)&po,   g_o);
    cudaGetSymbolAddress((void**)&pah,  g_ah);
    cudaGetSymbolAddress((void**)&pal,  g_al);
    cudaGetSymbolAddress((void**)&pakh, g_akh);
    cudaGetSymbolAddress((void**)&pakl, g_akl);
    cudaGetSymbolAddress((void**)&pavh, g_avh);
    cudaGetSymbolAddress((void**)&pavl, g_avl);
    cudaGetSymbolAddress((void**)&pwth, g_wth);
    cudaGetSymbolAddress((void**)&pwkh, g_wkth);
    cudaGetSymbolAddress((void**)&pwvh, g_wvth);
    cudaGetSymbolAddress((void**)&pqh,  g_qh);
    cudaGetSymbolAddress((void**)&pkh,  g_kh);
    cudaGetSymbolAddress((void**)&pvh,  g_vh);
    cudaGetSymbolAddress((void**)&prope, g_rope);

    cudaFuncSetAttribute(gemm_mma_big, cudaFuncAttributeMaxDynamicSharedMemorySize,
                         BG_SMEM);
    cudaFuncSetAttribute(gemm_mma_qkv, cudaFuncAttributeMaxDynamicSharedMemorySize,
                         BG_SMEM);
    cudaFuncSetAttribute(flash_mma_kernel, cudaFuncAttributeMaxDynamicSharedMemorySize,
                         FLASH_SMEM);

    const int XS_GRID = (NTOK*D_/4)/256;

    // 1) RoPE table + fused mix/split + merged weight transposes
    rope_fill_kernel<<<(T_*64)/256, 256>>>(prope);
    mix_split_kernel<<<XS_GRID, 256>>>(xq, xk, xv, mk, mv,
                                       pah, pal, pakh, pakl, pavh, pavl);
    wsplit_all_kernel<<<3584, dim3(32, 32)>>>(Wq, Wg, Wk, Wv, Wo,
                                              pwth, pwkh, pwvh);

    // 2) fused q/k/v/g projections: single 640-tile launch
    gemm_mma_qkv<<<QKV_TILES, 256, BG_SMEM>>>(
        pah, pal, pakh, pakl, pavh, pavl,
        pwth, pwkh, pwvh,
        pq, pg, pk, pv);

    // 3) fused per-head RMS norm (+RoPE via table), single fp16 out
    norm_all_kernel<<<NQBLK + 2*NKBLK, 128>>>(pq, pk, pv, prope,
                                              pqh, pkh, pvh);

    // 4) causal GQA attention + fused L2-norm/gate/split epilogue
    flash_mma_kernel<<<dim3(T_/128, B_*H_), 256, FLASH_SMEM>>>(
        pqh, pkh, pvh, pg, pah, pal);

    // 5) output projection (Wo transposed upfront at pwth + 2*D*D)
    gemm_mma_big<<<dim3(D_/128, NTOK/256), 256, BG_SMEM>>>(
        pah, pal, pwth + (size_t)2*D_*D_, po, nullptr, D_);

    // 6) final RMS norm + 1/sqrt(2*N_LAYER)
    final_norm_kernel<<<NTOK, 256>>>(po, out);
}

// round 15
// speedup vs baseline: 2.0384x; 1.4132x over previous
#include <cuda_runtime.h>
#include <cuda_fp16.h>
#include <math.h>
#include <stdint.h>

#define B_    2
#define T_    2048
#define D_    2048
#define H_    16
#define KVH_  4
#define HD_   128
#define NTOK  (B_*T_)

// ---------------- scratch (device globals: allocation-free) ----------------
__device__ float g_q  [NTOK*D_];
__device__ float g_k  [NTOK*KVH_*HD_];
__device__ float g_v  [NTOK*KVH_*HD_];
__device__ float g_g  [NTOK*D_];
__device__ float g_o  [NTOK*D_];
// single-fp16 operands
__device__ __align__(16) __half g_ah [NTOK*D_];      /* xq, later attn output */
__device__ __align__(16) __half g_akh[NTOK*D_];
__device__ __align__(16) __half g_avh[NTOK*D_];
__device__ __align__(16) __half g_wth [3*D_*D_];     /* Wq | Wg | Wo */
__device__ __align__(16) __half g_wkth[512*D_];
__device__ __align__(16) __half g_wvth[512*D_];
// attention operands
__device__ __align__(16) __half g_qh [NTOK*D_];
__device__ __align__(16) __half g_kh [NTOK*KVH_*HD_];
__device__ __align__(16) __half g_vh [NTOK*KVH_*HD_];
// RoPE table
__device__ __align__(16) float2 g_rope[T_*64];

// ================= baseline-ISA helpers =================
__device__ __forceinline__ uint32_t smem_u32(const void* p) {
    uint32_t a;
    asm("{ .reg .u64 t; cvta.to.shared.u64 t, %1; cvt.u32.u64 %0, t; }" : "=r"(a) : "l"(p));
    return a;
}
__device__ __forceinline__ uint32_t sw128(uint32_t off) { return off ^ ((off >> 3) & 0x70); }
__device__ __forceinline__ uint32_t sw256(uint32_t off) { return off ^ ((off >> 4) & 0x70); }

__device__ __forceinline__ void cp_async16(uint32_t dst, const void* src) {
    asm volatile("cp.async.cg.shared.global [%0], [%1], 16;" :: "r"(dst), "l"(src) : "memory");
}
#define CP_COMMIT() asm volatile("cp.async.commit_group;" ::: "memory")
#define CP_WAIT(n)  asm volatile("cp.async.wait_group %0;" :: "n"(n) : "memory")

__device__ __forceinline__ void ldsm_x4(uint32_t* r, uint32_t addr) {
    asm volatile("ldmatrix.sync.aligned.m8n8.x4.shared.b16 {%0,%1,%2,%3}, [%4];"
                 : "=r"(r[0]), "=r"(r[1]), "=r"(r[2]), "=r"(r[3]) : "r"(addr));
}
__device__ __forceinline__ void ldsm_x4_t(uint32_t* r, uint32_t addr) {
    asm volatile("ldmatrix.sync.aligned.m8n8.x4.trans.shared.b16 {%0,%1,%2,%3}, [%4];"
                 : "=r"(r[0]), "=r"(r[1]), "=r"(r[2]), "=r"(r[3]) : "r"(addr));
}
__device__ __forceinline__ void mma16816(float* d, const uint32_t* a, const uint32_t* b) {
    asm volatile("mma.sync.aligned.m16n8k16.row.col.f32.f16.f16.f32 "
                 "{%0,%1,%2,%3}, {%4,%5,%6,%7}, {%8,%9}, {%0,%1,%2,%3};"
                 : "+f"(d[0]), "+f"(d[1]), "+f"(d[2]), "+f"(d[3])
                 : "r"(a[0]), "r"(a[1]), "r"(a[2]), "r"(a[3]), "r"(b[0]), "r"(b[1]));
}

// fast exp on the FMA pipe
__device__ __forceinline__ float fast_exp(float x) {
    x = fmaxf(x, -80.f);
    const float LOG2E = 1.4426950408889634f;
    float t = x * LOG2E;
    float r = t + 12582912.f;
    float i = r - 12582912.f;
    float f = t - i;
    uint32_t ib = __float_as_uint(r);
    float sc = __uint_as_float((ib + 127u) << 23);
    float p = 1.3333558146e-3f;
    p = fmaf(p, f, 9.6181291076e-3f);
    p = fmaf(p, f, 5.5504108664e-2f);
    p = fmaf(p, f, 2.4022650696e-1f);
    p = fmaf(p, f, 6.9314718056e-1f);
    p = fmaf(p, f, 1.0f);
    return p * sc;
}

__device__ __forceinline__ void split2h(float a, float b, uint32_t& hp, uint32_t& lp) {
    __half ha = __float2half_rn(a), hb = __float2half_rn(b);
    __half la = __float2half_rn(a - __half2float(ha));
    __half lb = __float2half_rn(b - __half2float(hb));
    hp = ((uint32_t)__half_as_ushort(hb) << 16) | __half_as_ushort(ha);
    lp = ((uint32_t)__half_as_ushort(lb) << 16) | __half_as_ushort(la);
}
__device__ __forceinline__ uint32_t pack2h(float a, float b) {
    __half ha = __float2half_rn(a), hb = __float2half_rn(b);
    return ((uint32_t)__half_as_ushort(hb) << 16) | __half_as_ushort(ha);
}

// ================= elementwise kernels =================
__global__ void rope_fill_kernel(float2* __restrict__ tab)
{
    int idx = blockIdx.x * blockDim.x + threadIdx.x;
    int t = idx >> 6, j = idx & 63;
    float inv_freq = exp2f(-(float)j * (13.287712379549449f / 64.f));
    float ang = (float)t * inv_freq;
    float sn, cs;
    sincosf(ang, &sn, &cs);
    tab[idx] = make_float2(cs, sn);
}

// fused: xq pack + time-shift mix + pack for k/v paths (single fp16)
__global__ void mix_split_kernel(const float* __restrict__ xq,
                                 const float* __restrict__ xk, const float* __restrict__ xv,
                                 const float* __restrict__ mk, const float* __restrict__ mv,
                                 __half* __restrict__ qo,
                                 __half* __restrict__ ko, __half* __restrict__ vo)
{
    const int D4 = D_ / 4;
    int idx = blockIdx.x * blockDim.x + threadIdx.x;
    int d4  = idx & (D4 - 1);
    int tok = idx >> 9;
    int t   = tok & (T_ - 1);

    {
        float4 v = ((const float4*)xq)[idx];
        ((uint2*)qo)[idx] = make_uint2(pack2h(v.x, v.y), pack2h(v.z, v.w));
    }

    float4 kc = ((const float4*)xk)[idx];
    float4 vc = ((const float4*)xv)[idx];
    float4 m1 = ((const float4*)mk)[d4];
    float4 m2 = ((const float4*)mv)[d4];
    float4 kp = make_float4(0.f,0.f,0.f,0.f);
    float4 vp = make_float4(0.f,0.f,0.f,0.f);
    if (t > 0) {
        kp = ((const float4*)xk)[idx - D4];
        vp = ((const float4*)xv)[idx - D4];
    }
    float4 r1, r2;
    r1.x = kc.x + m1.x*(kp.x-kc.x);  r1.y = kc.y + m1.y*(kp.y-kc.y);
    r1.z = kc.z + m1.z*(kp.z-kc.z);  r1.w = kc.w + m1.w*(kp.w-kc.w);
    r2.x = vc.x + m2.x*(vp.x-vc.x);  r2.y = vc.y + m2.y*(vp.y-vc.y);
    r2.z = vc.z + m2.z*(vp.z-vc.z);  r2.w = vc.w + m2.w*(vp.w-vc.w);

    ((uint2*)ko)[idx] = make_uint2(pack2h(r1.x, r1.y), pack2h(r1.z, r1.w));
    ((uint2*)vo)[idx] = make_uint2(pack2h(r2.x, r2.y), pack2h(r2.z, r2.w));
}

// ---- merged weight transpose: all 5 weights in one flat-grid launch ----
__device__ __forceinline__ void wsplit_body(const float* __restrict__ W,
                                            __half* __restrict__ th, int N,
                                            int bx, int by)
{
    __shared__ float s[32][132];
    const int k0 = by * 128, n0 = bx * 32;
    const int tx = threadIdx.x, ty = threadIdx.y;
    const int tid = ty * 32 + tx;

#pragma unroll
    for (int i = 0; i < 4; i++) {
        int kk = ty + 32*i;
        s[tx][kk] = W[(size_t)(k0 + kk) * N + n0 + tx];
    }
    __syncthreads();

    const int r = tid >> 5, seg = tid & 31;
    float4 v = *(const float4*)(&s[r][seg << 2]);
    size_t o = ((size_t)(n0 + r) * D_ + k0 + (seg << 2)) >> 2;
    ((uint2*)th)[o] = make_uint2(pack2h(v.x, v.y), pack2h(v.z, v.w));
}

__global__ void wsplit_all_kernel(const float* __restrict__ Wq, const float* __restrict__ Wg,
                                  const float* __restrict__ Wk, const float* __restrict__ Wv,
                                  const float* __restrict__ Wo,
                                  __half* __restrict__ wqg_o, __half* __restrict__ wk,
                                  __half* __restrict__ wv)
{
    const int idx = blockIdx.x;
    if (idx < 1024) {
        wsplit_body(Wq, wqg_o, D_, idx & 63, idx >> 6);
    } else if (idx < 2048) {
        const int i = idx - 1024;
        wsplit_body(Wg, wqg_o + (size_t)D_*D_, D_, i & 63, i >> 6);
    } else if (idx < 2304) {
        const int i = idx - 2048;
        wsplit_body(Wk, wk, 512, i & 15, i >> 4);
    } else if (idx < 2560) {
        const int i = idx - 2304;
        wsplit_body(Wv, wv, 512, i & 15, i >> 4);
    } else {
        const int i = idx - 2560;
        wsplit_body(Wo, wqg_o + (size_t)2*D_*D_, D_, i & 63, i >> 6);
    }
}

#define GK  2048
#define NCH (GK/64)

// ============ BIG GEMM body: 256x128 block, 64x64 warps, single fp16 =======
#define BG_A     32768
#define BG_B     16384
#define BG_STAGE (BG_A + BG_B)           /* 48 KB */
#define BG_SMEM  (2*BG_STAGE + 1024)

__device__ __forceinline__ void gemm_big_body(
    const __half* __restrict__ ah,
    const __half* __restrict__ wth,
    float* __restrict__ C0, float* __restrict__ C1, int cstride,
    int m0, int n0, char* sm)
{
    const uint32_t smb   = smem_u32(sm);
    const uint32_t tiles = (smb + 1023u) & ~1023u;

    const int tid  = threadIdx.x;
    const int wid  = tid >> 5, lane = tid & 31;
    const int wm   = wid & 3,  wn   = wid >> 2;

    const __half* pAh = ah  + (size_t)m0 * GK;
    const __half* pB  = wth + (size_t)n0 * GK;

    float acc[4][8][4];
#pragma unroll
    for (int i = 0; i < 4; i++)
#pragma unroll
        for (int j = 0; j < 8; j++)
#pragma unroll
            for (int q = 0; q < 4; q++) acc[i][j][q] = 0.f;

    auto prefetch = [&](int ch) {
        const uint32_t stage = tiles + (uint32_t)(ch & 1) * BG_STAGE;
        const int ke = ch << 6;
#pragma unroll
        for (int j = 0; j < 8; j++) {
            int idx = tid + (j << 8);
            int r = idx >> 3, c = idx & 7;
            uint32_t off = sw128((r << 7) + (c << 4));
            cp_async16(stage + off, pAh + (size_t)r * GK + ke + (c << 3));
        }
#pragma unroll
        for (int j = 0; j < 4; j++) {
            int idx = tid + (j << 8);
            int r = idx >> 3, c = idx & 7;
            uint32_t off = sw128((r << 7) + (c << 4));
            cp_async16(stage + BG_A + off, pB + (size_t)r * GK + ke + (c << 3));
        }
        CP_COMMIT();
    };

    prefetch(0);

    for (int ch = 0; ch < NCH; ch++) {
        if (ch + 1 < NCH) { prefetch(ch + 1); CP_WAIT(1); }
        else              { CP_WAIT(0); }
        __syncthreads();

        const uint32_t stage = tiles + (uint32_t)(ch & 1) * BG_STAGE;
        const uint32_t sAh = stage, sB = stage + BG_A;

#pragma unroll
        for (int ks = 0; ks < 4; ks++) {
            const int kb = ks << 5;

            uint32_t ahf[4][4];
#pragma unroll
            for (int mt = 0; mt < 4; mt++) {
                int row = wm*64 + mt*16 + (lane & 15);
                uint32_t off = sw128((uint32_t)(row << 7) + kb + ((lane >> 4) << 4));
                ldsm_x4(ahf[mt], sAh + off);
            }
            const int brow = wn*64 + (lane & 7) + ((lane >> 4) << 3);
            const int bko  = kb + (((lane >> 3) & 1) << 4);
#pragma unroll
            for (int np = 0; np < 4; np++) {
                uint32_t bh[4];
                uint32_t off = sw128((uint32_t)((brow + np*16) << 7) + bko);
                ldsm_x4(bh, sB + off);
#pragma unroll
                for (int mt = 0; mt < 4; mt++) {
                    mma16816(acc[mt][2*np],   ahf[mt], bh);
                    mma16816(acc[mt][2*np+1], ahf[mt], bh + 2);
                }
            }
        }
        __syncthreads();
    }

    float* C = C0;
    int nc = n0;
    if (C1 != nullptr && n0 >= cstride) { C = C1; nc = n0 - cstride; }

    const int er = lane >> 2, ec = (lane & 3) << 1;
#pragma unroll
    for (int mt = 0; mt < 4; mt++) {
        int r0 = m0 + wm*64 + mt*16 + er;
#pragma unroll
        for (int nt = 0; nt < 8; nt++) {
            int c = nc + wn*64 + nt*8 + ec;
            *(float2*)(C + (size_t)r0      * cstride + c) = make_float2(acc[mt][nt][0], acc[mt][nt][1]);
            *(float2*)(C + (size_t)(r0 + 8)* cstride + c) = make_float2(acc[mt][nt][2], acc[mt][nt][3]);
        }
    }
}

__global__ void __launch_bounds__(256, 1) gemm_mma_big(
    const __half* __restrict__ ah,
    const __half* __restrict__ wth,
    float* __restrict__ C0, float* __restrict__ C1, int cstride)
{
    extern __shared__ char sm[];
    gemm_big_body(ah, wth, C0, C1, cstride,
                  blockIdx.y << 8, blockIdx.x << 7, sm);
}

#define QKV_TILES 640
__global__ void __launch_bounds__(256, 1) gemm_mma_qkv(
    const __half* __restrict__ aqh,
    const __half* __restrict__ akh,
    const __half* __restrict__ avh,
    const __half* __restrict__ wqh, const __half* __restrict__ wkh,
    const __half* __restrict__ wvh,
    float* __restrict__ pq, float* __restrict__ pg,
    float* __restrict__ pk, float* __restrict__ pv)
{
    extern __shared__ char sm[];
    const int idx = blockIdx.x;
    if (idx < 512) {
        gemm_big_body(aqh, wqh, pq, pg, D_,
                      (idx >> 5) << 8, (idx & 31) << 7, sm);
    } else if (idx < 576) {
        const int i = idx - 512;
        gemm_big_body(akh, wkh, pk, nullptr, 512,
                      (i >> 2) << 8, (i & 3) << 7, sm);
    } else {
        const int i = idx - 576;
        gemm_big_body(avh, wvh, pv, nullptr, 512,
                      (i >> 2) << 8, (i & 3) << 7, sm);
    }
}

// ---- fused per-head RMS norm (+RoPE via table), single fp16 output ----
__device__ __forceinline__ void norm_head_body(
    const float* __restrict__ x, int heads, int do_rope, float scale,
    const float2* __restrict__ rope,
    __half* __restrict__ oh, int blk)
{
    __shared__ float sbuf[4];
    __shared__ float svals[128];
    const int head = blk % heads;
    const int tok  = blk / heads;
    const int t    = tok % T_;
    const size_t base = (size_t)tok*heads*HD_ + head*HD_;
    const float* p = x + base;
    const int d = threadIdx.x;

    float v  = p[d];
    float ss = v*v;
#pragma unroll
    for (int o = 16; o > 0; o >>= 1) ss += __shfl_xor_sync(0xffffffffu, ss, o);
    if ((d & 31) == 0) sbuf[d >> 5] = ss;
    __syncthreads();
    float tot = sbuf[0] + sbuf[1] + sbuf[2] + sbuf[3];
    float r   = rsqrtf(tot * (1.f/HD_) + 1e-8f);
    float vn  = v * r;
    float f;

    if (do_rope) {
        svals[d] = vn;
        __syncthreads();
        int   j  = d & 63;
        float2 cs = rope[t*64 + j];
        float partner = svals[d ^ 64];
        f = (d < 64) ? (vn*cs.x - partner*cs.y) : (vn*cs.x + partner*cs.y);
    } else {
        f = vn;
    }
    f *= scale;
    oh[base + d] = __float2half_rn(f);
}

#define NQBLK (NTOK*H_)
#define NKBLK (NTOK*KVH_)
__global__ void norm_all_kernel(
    const float* __restrict__ pq, const float* __restrict__ pk, const float* __restrict__ pv,
    const float2* __restrict__ rope,
    __half* __restrict__ qh, __half* __restrict__ kh, __half* __restrict__ vh)
{
    const int blk = blockIdx.x;
    if (blk < NQBLK) {
        norm_head_body(pq, H_, 1, 0.08838834764831845f, rope, qh, blk);
    } else if (blk < NQBLK + NKBLK) {
        norm_head_body(pk, KVH_, 1, 1.f, rope, kh, blk - NQBLK);
    } else {
        norm_head_body(pv, KVH_, 0, 1.f, rope, vh, blk - NQBLK - NKBLK);
    }
}

// ================= flash attention: Q/K/V single fp16, P split =============
#define FQH  0
#define FKV  32768
#define FSTG 32768
#define FLASH_SMEM (FKV + 2*FSTG)

__global__ void __launch_bounds__(256, 1) flash_mma_kernel(
    const __half* __restrict__ qh,
    const __half* __restrict__ kh, const __half* __restrict__ vh,
    const float* __restrict__ g,
    __half* __restrict__ oh_out)
{
    extern __shared__ char sm[];
    const uint32_t smb = smem_u32(sm);

    const int tid  = threadIdx.x;
    const int w    = tid >> 5, lane = tid & 31;
    const int qt   = (gridDim.x - 1) - blockIdx.x;
    const int b    = blockIdx.y >> 4;
    const int h    = blockIdx.y & 15;
    const int kvh  = h >> 2;
    const int qs   = qt << 7;

    {
        const __half* qg = qh + ((size_t)(b*T_ + qs))*D_ + h*HD_;
#pragma unroll
        for (int it = 0; it < 8; it++) {
            int idx = tid + (it << 8);
            int r = idx >> 4, c = idx & 15;
            cp_async16(smb + FQH + sw256((r << 8) + (c << 4)),
                       qg + (size_t)r*D_ + (c << 3));
        }
        CP_COMMIT();
    }

    const __half* kh_b = kh + (size_t)(b*T_)*(KVH_*HD_) + kvh*HD_;
    const __half* vh_b = vh + (size_t)(b*T_)*(KVH_*HD_) + kvh*HD_;

    auto prefetch_kv = [&](int kt) {
        const uint32_t sb = smb + FKV + (uint32_t)(kt & 1)*FSTG;
        const size_t rb = (size_t)(kt << 6) * (KVH_*HD_);
        const __half* ps[2] = { kh_b + rb, vh_b + rb };
#pragma unroll
        for (int t = 0; t < 2; t++) {
#pragma unroll
            for (int it = 0; it < 4; it++) {
                int idx = tid + (it << 8);
                int r = idx >> 4, c = idx & 15;
                cp_async16(sb + t*16384 + sw256((r << 8) + (c << 4)),
                           ps[t] + (size_t)r*(KVH_*HD_) + (c << 3));
            }
        }
        CP_COMMIT();
    };

    prefetch_kv(0);

    uint32_t aQh[8][4];
    CP_WAIT(1);
    __syncthreads();
#pragma unroll
    for (int ks8 = 0; ks8 < 8; ks8++) {
        int row = (w << 4) + (lane & 15);
        uint32_t off = sw256((uint32_t)(row << 8) + (ks8 << 5) + ((lane >> 4) << 4));
        ldsm_x4(aQh[ks8], smb + FQH + off);
    }

    float o[16][4];
#pragma unroll
    for (int nh = 0; nh < 16; nh++)
#pragma unroll
        for (int qq = 0; qq < 4; qq++) o[nh][qq] = 0.f;
    float m0 = -1e30f, m1 = -1e30f, l0 = 0.f, l1 = 0.f;

    const int nkv = 2*qt + 2;
    for (int kt = 0; kt < nkv; kt++) {
        const int ks = kt << 6;
        if (kt + 1 < nkv) { prefetch_kv(kt + 1); CP_WAIT(1); }
        else              { CP_WAIT(0); }
        __syncthreads();

        const uint32_t sb  = smb + FKV + (uint32_t)(kt & 1)*FSTG;
        const uint32_t sKH = sb, sVH = sb + 16384;

        float s[8][4];
#pragma unroll
        for (int nt = 0; nt < 8; nt++)
#pragma unroll
            for (int qq = 0; qq < 4; qq++) s[nt][qq] = 0.f;

#pragma unroll
        for (int ks8 = 0; ks8 < 8; ks8++) {
            const int kb = ks8 << 5;
            uint32_t bhf[4][4];
            const int brow4 = (lane & 7) + ((lane >> 4) << 3);
            const int bko   = kb + (((lane >> 3) & 1) << 4);
#pragma unroll
            for (int np = 0; np < 4; np++) {
                uint32_t off = sw256((uint32_t)((brow4 + np*16) << 8) + bko);
                ldsm_x4(bhf[np], sKH + off);
            }
#pragma unroll
            for (int np = 0; np < 4; np++) {
                mma16816(s[2*np],   aQh[ks8], bhf[np]);
                mma16816(s[2*np+1], aQh[ks8], bhf[np] + 2);
            }
        }

        if (kt >= 2*qt) {
            const int gr0 = qs + (w << 4) + (lane >> 2);
            const int gc0 = ks + ((lane & 3) << 1);
#pragma unroll
            for (int nt = 0; nt < 8; nt++) {
                int c = gc0 + nt*8;
                if (c     > gr0)     s[nt][0] = -1e30f;
                if (c + 1 > gr0)     s[nt][1] = -1e30f;
                if (c     > gr0 + 8) s[nt][2] = -1e30f;
                if (c + 1 > gr0 + 8) s[nt][3] = -1e30f;
            }
        }

        float mx0 = -1e30f, mx1 = -1e30f;
#pragma unroll
        for (int nt = 0; nt < 8; nt++) {
            mx0 = fmaxf(mx0, fmaxf(s[nt][0], s[nt][1]));
            mx1 = fmaxf(mx1, fmaxf(s[nt][2], s[nt][3]));
        }
        mx0 = fmaxf(mx0, __shfl_xor_sync(0xffffffffu, mx0, 1));
        mx0 = fmaxf(mx0, __shfl_xor_sync(0xffffffffu, mx0, 2));
        mx1 = fmaxf(mx1, __shfl_xor_sync(0xffffffffu, mx1, 1));
        mx1 = fmaxf(mx1, __shfl_xor_sync(0xffffffffu, mx1, 2));
        float m0n = fmaxf(m0, mx0), m1n = fmaxf(m1, mx1);
        float sc0 = fast_exp(m0 - m0n), sc1 = fast_exp(m1 - m1n);
        m0 = m0n; m1 = m1n;

        float sum0 = 0.f, sum1 = 0.f;
#pragma unroll
        for (int nt = 0; nt < 8; nt++) {
            s[nt][0] = fast_exp(s[nt][0] - m0n); sum0 += s[nt][0];
            s[nt][1] = fast_exp(s[nt][1] - m0n); sum0 += s[nt][1];
            s[nt][2] = fast_exp(s[nt][2] - m1n); sum1 += s[nt][2];
            s[nt][3] = fast_exp(s[nt][3] - m1n); sum1 += s[nt][3];
        }
        sum0 += __shfl_xor_sync(0xffffffffu, sum0, 1);
        sum0 += __shfl_xor_sync(0xffffffffu, sum0, 2);
        sum1 += __shfl_xor_sync(0xffffffffu, sum1, 1);
        sum1 += __shfl_xor_sync(0xffffffffu, sum1, 2);
        l0 = l0*sc0 + sum0;
        l1 = l1*sc1 + sum1;

#pragma unroll
        for (int nh = 0; nh < 16; nh++) {
            o[nh][0] *= sc0; o[nh][1] *= sc0;
            o[nh][2] *= sc1; o[nh][3] *= sc1;
        }

        // ---- O += P V (P split, V single) ----
#pragma unroll
        for (int j = 0; j < 4; j++) {
            uint32_t aPh[4], aPl[4];
            split2h(s[2*j][0],   s[2*j][1],   aPh[0], aPl[0]);
            split2h(s[2*j][2],   s[2*j][3],   aPh[1], aPl[1]);
            split2h(s[2*j+1][0], s[2*j+1][1], aPh[2], aPl[2]);
            split2h(s[2*j+1][2], s[2*j+1][3], aPh[3], aPl[3]);
            const uint32_t vrow = (j << 4) + (lane & 15);
            const uint32_t nsel = (lane >> 4);
#pragma unroll
            for (int pp = 0; pp < 4; pp++) {
                uint32_t bh0[4], bh1[4];
                uint32_t off0 = sw256((vrow << 8) + ((4*pp     + nsel) << 4));
                uint32_t off1 = sw256((vrow << 8) + ((4*pp + 2 + nsel) << 4));
                ldsm_x4_t(bh0, sVH + off0);
                ldsm_x4_t(bh1, sVH + off1);
                mma16816(o[4*pp],   aPh, bh0);
                mma16816(o[4*pp+1], aPh, bh0 + 2);
                mma16816(o[4*pp+2], aPh, bh1);
                mma16816(o[4*pp+3], aPh, bh1 + 2);
                mma16816(o[4*pp],   aPl, bh0);
                mma16816(o[4*pp+1], aPl, bh0 + 2);
                mma16816(o[4*pp+2], aPl, bh1);
                mma16816(o[4*pp+3], aPl, bh1 + 2);
            }
        }
        __syncthreads();
    }

    // ---- fused epilogue: 1/l, per-head L2 norm, gate, single fp16 out ----
    const float inv0 = 1.f / l0, inv1 = 1.f / l1;
    float y0[16][2], y1[16][2];
    float ss0 = 0.f, ss1 = 0.f;
#pragma unroll
    for (int nh = 0; nh < 16; nh++) {
        y0[nh][0] = o[nh][0]*inv0;  y0[nh][1] = o[nh][1]*inv0;
        y1[nh][0] = o[nh][2]*inv1;  y1[nh][1] = o[nh][3]*inv1;
        ss0 += y0[nh][0]*y0[nh][0] + y0[nh][1]*y0[nh][1];
        ss1 += y1[nh][0]*y1[nh][0] + y1[nh][1]*y1[nh][1];
    }
    ss0 += __shfl_xor_sync(0xffffffffu, ss0, 1);
    ss0 += __shfl_xor_sync(0xffffffffu, ss0, 2);
    ss1 += __shfl_xor_sync(0xffffffffu, ss1, 1);
    ss1 += __shfl_xor_sync(0xffffffffu, ss1, 2);
    const float s0 = 1.f / fmaxf(sqrtf(ss0), 1e-12f);
    const float s1 = 1.f / fmaxf(sqrtf(ss1), 1e-12f);

    const int r0 = qs + (w << 4) + (lane >> 2);
    const size_t base0 = ((size_t)(b*T_) + r0)*D_ + h*HD_ + ((lane & 3) << 1);
    const size_t base1 = base0 + (size_t)8*D_;
#pragma unroll
    for (int nh = 0; nh < 16; nh++) {
        float2 gv0 = *(const float2*)(g + base0 + nh*8);
        float2 gv1 = *(const float2*)(g + base1 + nh*8);
        *(uint32_t*)(oh_out + base0 + nh*8) =
            pack2h(gv0.x*y0[nh][0]*s0, gv0.y*y0[nh][1]*s0);
        *(uint32_t*)(oh_out + base1 + nh*8) =
            pack2h(gv1.x*y1[nh][0]*s1, gv1.y*y1[nh][1]*s1);
    }
}

// ---------------- final RMS norm over D, scaled by 1/sqrt(48) ----------------
__global__ void final_norm_kernel(const float* __restrict__ in, float* __restrict__ out)
{
    __shared__ float sbuf[8];
    const int tok = blockIdx.x;
    const float* p = in + (size_t)tok*D_;
    const int base = threadIdx.x * 8;

    float4 a = *(const float4*)(p + base);
    float4 b = *(const float4*)(p + base + 4);
    float ss = a.x*a.x + a.y*a.y + a.z*a.z + a.w*a.w
             + b.x*b.x + b.y*b.y + b.z*b.z + b.w*b.w;
#pragma unroll
    for (int o = 16; o > 0; o >>= 1) ss += __shfl_xor_sync(0xffffffffu, ss, o);
    if ((threadIdx.x & 31) == 0) sbuf[threadIdx.x >> 5] = ss;
    __syncthreads();
    float tot = 0.f;
#pragma unroll
    for (int i = 0; i < 8; i++) tot += sbuf[i];
    float r = rsqrtf(tot * (1.f/D_) + 1e-8f) * 0.14433756729740643f;

    float* q = out + (size_t)tok*D_;
    a.x*=r; a.y*=r; a.z*=r; a.w*=r;
    b.x*=r; b.y*=r; b.z*=r; b.w*=r;
    *(float4*)(q + base)     = a;
    *(float4*)(q + base + 4) = b;
}

// ---------------- launcher ----------------
extern "C" void kernel_launch(void* const* d_in, const int* in_sizes, int n_in,
                              void* d_out, int out_size)
{
    (void)in_sizes; (void)n_in; (void)out_size;
    const float* xq = (const float*)d_in[0];
    const float* xk = (const float*)d_in[1];
    const float* xv = (const float*)d_in[2];
    const float* Wq = (const float*)d_in[3];
    const float* Wk = (const float*)d_in[4];
    const float* Wv = (const float*)d_in[5];
    const float* Wg = (const float*)d_in[6];
    const float* Wo = (const float*)d_in[7];
    const float* mk = (const float*)d_in[8];
    const float* mv = (const float*)d_in[9];
    float* out = (float*)d_out;

    float *pq, *pk, *pv, *pg, *po;
    __half *pah, *pakh, *pavh, *pwth, *pwkh, *pwvh;
    __half *pqh, *pkh, *pvh;
    float2* prope;
    cudaGetSymbolAddress((void**)&pq,   g_q);
    cudaGetSymbolAddress((void**)&pk,   g_k);
    cudaGetSymbolAddress((void**)&pv,   g_v);
    cudaGetSymbolAddress((void**)&pg,   g_g);
    cudaGetSymbolAddress((void**)&po,   g_o);
    cudaGetSymbolAddress((void**)&pah,  g_ah);
    cudaGetSymbolAddress((void**)&pakh, g_akh);
    cudaGetSymbolAddress((void**)&pavh, g_avh);
    cudaGetSymbolAddress((void**)&pwth, g_wth);
    cudaGetSymbolAddress((void**)&pwkh, g_wkth);
    cudaGetSymbolAddress((void**)&pwvh, g_wvth);
    cudaGetSymbolAddress((void**)&pqh,  g_qh);
    cudaGetSymbolAddress((void**)&pkh,  g_kh);
    cudaGetSymbolAddress((void**)&pvh,  g_vh);
    cudaGetSymbolAddress((void**)&prope, g_rope);

    cudaFuncSetAttribute(gemm_mma_big, cudaFuncAttributeMaxDynamicSharedMemorySize,
                         BG_SMEM);
    cudaFuncSetAttribute(gemm_mma_qkv, cudaFuncAttributeMaxDynamicSharedMemorySize,
                         BG_SMEM);
    cudaFuncSetAttribute(flash_mma_kernel, cudaFuncAttributeMaxDynamicSharedMemorySize,
                         FLASH_SMEM);

    const int XS_GRID = (NTOK*D_/4)/256;

    // 1) RoPE table + fused mix/pack + merged weight transposes
    rope_fill_kernel<<<(T_*64)/256, 256>>>(prope);
    mix_split_kernel<<<XS_GRID, 256>>>(xq, xk, xv, mk, mv, pah, pakh, pavh);
    wsplit_all_kernel<<<3584, dim3(32, 32)>>>(Wq, Wg, Wk, Wv, Wo,
                                              pwth, pwkh, pwvh);

    // 2) fused q/k/v/g projections (single fp16)
    gemm_mma_qkv<<<QKV_TILES, 256, BG_SMEM>>>(
        pah, pakh, pavh, pwth, pwkh, pwvh,
        pq, pg, pk, pv);

    // 3) fused per-head RMS norm (+RoPE via table)
    norm_all_kernel<<<NQBLK + 2*NKBLK, 128>>>(pq, pk, pv, prope,
                                              pqh, pkh, pvh);

    // 4) causal GQA attention + fused L2-norm/gate epilogue (single fp16 out)
    flash_mma_kernel<<<dim3(T_/128, B_*H_), 256, FLASH_SMEM>>>(
        pqh, pkh, pvh, pg, pah);

    // 5) output projection (single fp16)
    gemm_mma_big<<<dim3(D_/128, NTOK/256), 256, BG_SMEM>>>(
        pah, pwth + (size_t)2*D_*D_, po, nullptr, D_);

    // 6) final RMS norm + 1/sqrt(2*N_LAYER)
    final_norm_kernel<<<NTOK, 256>>>(po, out);
}

// round 16
// speedup vs baseline: 2.1950x; 1.0769x over previous
#include <cuda_runtime.h>
#include <cuda_fp16.h>
#include <math.h>
#include <stdint.h>

#define B_    2
#define T_    2048
#define D_    2048
#define H_    16
#define KVH_  4
#define HD_   128
#define NTOK  (B_*T_)

// ---------------- scratch (device globals: allocation-free) ----------------
__device__ float g_q  [NTOK*D_];
__device__ float g_k  [NTOK*KVH_*HD_];
__device__ float g_v  [NTOK*KVH_*HD_];
__device__ float g_g  [NTOK*D_];
__device__ float g_o  [NTOK*D_];
// single-fp16 operands
__device__ __align__(16) __half g_ah [NTOK*D_];      /* xq, later attn output */
__device__ __align__(16) __half g_akh[NTOK*D_];
__device__ __align__(16) __half g_avh[NTOK*D_];
__device__ __align__(16) __half g_wth [3*D_*D_];     /* Wq | Wg | Wo */
__device__ __align__(16) __half g_wkth[512*D_];
__device__ __align__(16) __half g_wvth[512*D_];
// attention operands
__device__ __align__(16) __half g_qh [NTOK*D_];
__device__ __align__(16) __half g_kh [NTOK*KVH_*HD_];
__device__ __align__(16) __half g_vh [NTOK*KVH_*HD_];
// RoPE table
__device__ __align__(16) float2 g_rope[T_*64];

// ================= baseline-ISA helpers =================
__device__ __forceinline__ uint32_t smem_u32(const void* p) {
    uint32_t a;
    asm("{ .reg .u64 t; cvta.to.shared.u64 t, %1; cvt.u32.u64 %0, t; }" : "=r"(a) : "l"(p));
    return a;
}
__device__ __forceinline__ uint32_t sw128(uint32_t off) { return off ^ ((off >> 3) & 0x70); }
__device__ __forceinline__ uint32_t sw256(uint32_t off) { return off ^ ((off >> 4) & 0x70); }

__device__ __forceinline__ void cp_async16(uint32_t dst, const void* src) {
    asm volatile("cp.async.cg.shared.global [%0], [%1], 16;" :: "r"(dst), "l"(src) : "memory");
}
#define CP_COMMIT() asm volatile("cp.async.commit_group;" ::: "memory")
#define CP_WAIT(n)  asm volatile("cp.async.wait_group %0;" :: "n"(n) : "memory")

__device__ __forceinline__ void ldsm_x4(uint32_t* r, uint32_t addr) {
    asm volatile("ldmatrix.sync.aligned.m8n8.x4.shared.b16 {%0,%1,%2,%3}, [%4];"
                 : "=r"(r[0]), "=r"(r[1]), "=r"(r[2]), "=r"(r[3]) : "r"(addr));
}
__device__ __forceinline__ void ldsm_x4_t(uint32_t* r, uint32_t addr) {
    asm volatile("ldmatrix.sync.aligned.m8n8.x4.trans.shared.b16 {%0,%1,%2,%3}, [%4];"
                 : "=r"(r[0]), "=r"(r[1]), "=r"(r[2]), "=r"(r[3]) : "r"(addr));
}
__device__ __forceinline__ void mma16816(float* d, const uint32_t* a, const uint32_t* b) {
    asm volatile("mma.sync.aligned.m16n8k16.row.col.f32.f16.f16.f32 "
                 "{%0,%1,%2,%3}, {%4,%5,%6,%7}, {%8,%9}, {%0,%1,%2,%3};"
                 : "+f"(d[0]), "+f"(d[1]), "+f"(d[2]), "+f"(d[3])
                 : "r"(a[0]), "r"(a[1]), "r"(a[2]), "r"(a[3]), "r"(b[0]), "r"(b[1]));
}

// fast exp on the FMA pipe
__device__ __forceinline__ float fast_exp(float x) {
    x = fmaxf(x, -80.f);
    const float LOG2E = 1.4426950408889634f;
    float t = x * LOG2E;
    float r = t + 12582912.f;
    float i = r - 12582912.f;
    float f = t - i;
    uint32_t ib = __float_as_uint(r);
    float sc = __uint_as_float((ib + 127u) << 23);
    float p = 1.3333558146e-3f;
    p = fmaf(p, f, 9.6181291076e-3f);
    p = fmaf(p, f, 5.5504108664e-2f);
    p = fmaf(p, f, 2.4022650696e-1f);
    p = fmaf(p, f, 6.9314718056e-1f);
    p = fmaf(p, f, 1.0f);
    return p * sc;
}

__device__ __forceinline__ uint32_t pack2h(float a, float b) {
    __half ha = __float2half_rn(a), hb = __float2half_rn(b);
    return ((uint32_t)__half_as_ushort(hb) << 16) | __half_as_ushort(ha);
}

// ================= elementwise kernels =================
__global__ void rope_fill_kernel(float2* __restrict__ tab)
{
    int idx = blockIdx.x * blockDim.x + threadIdx.x;
    int t = idx >> 6, j = idx & 63;
    float inv_freq = exp2f(-(float)j * (13.287712379549449f / 64.f));
    float ang = (float)t * inv_freq;
    float sn, cs;
    sincosf(ang, &sn, &cs);
    tab[idx] = make_float2(cs, sn);
}

// fused: xq pack + time-shift mix + pack for k/v paths (single fp16)
__global__ void mix_split_kernel(const float* __restrict__ xq,
                                 const float* __restrict__ xk, const float* __restrict__ xv,
                                 const float* __restrict__ mk, const float* __restrict__ mv,
                                 __half* __restrict__ qo,
                                 __half* __restrict__ ko, __half* __restrict__ vo)
{
    const int D4 = D_ / 4;
    int idx = blockIdx.x * blockDim.x + threadIdx.x;
    int d4  = idx & (D4 - 1);
    int tok = idx >> 9;
    int t   = tok & (T_ - 1);

    {
        float4 v = ((const float4*)xq)[idx];
        ((uint2*)qo)[idx] = make_uint2(pack2h(v.x, v.y), pack2h(v.z, v.w));
    }

    float4 kc = ((const float4*)xk)[idx];
    float4 vc = ((const float4*)xv)[idx];
    float4 m1 = ((const float4*)mk)[d4];
    float4 m2 = ((const float4*)mv)[d4];
    float4 kp = make_float4(0.f,0.f,0.f,0.f);
    float4 vp = make_float4(0.f,0.f,0.f,0.f);
    if (t > 0) {
        kp = ((const float4*)xk)[idx - D4];
        vp = ((const float4*)xv)[idx - D4];
    }
    float4 r1, r2;
    r1.x = kc.x + m1.x*(kp.x-kc.x);  r1.y = kc.y + m1.y*(kp.y-kc.y);
    r1.z = kc.z + m1.z*(kp.z-kc.z);  r1.w = kc.w + m1.w*(kp.w-kc.w);
    r2.x = vc.x + m2.x*(vp.x-vc.x);  r2.y = vc.y + m2.y*(vp.y-vc.y);
    r2.z = vc.z + m2.z*(vp.z-vc.z);  r2.w = vc.w + m2.w*(vp.w-vc.w);

    ((uint2*)ko)[idx] = make_uint2(pack2h(r1.x, r1.y), pack2h(r1.z, r1.w));
    ((uint2*)vo)[idx] = make_uint2(pack2h(r2.x, r2.y), pack2h(r2.z, r2.w));
}

// ---- merged weight transpose: all 5 weights in one flat-grid launch ----
__device__ __forceinline__ void wsplit_body(const float* __restrict__ W,
                                            __half* __restrict__ th, int N,
                                            int bx, int by)
{
    __shared__ float s[32][132];
    const int k0 = by * 128, n0 = bx * 32;
    const int tx = threadIdx.x, ty = threadIdx.y;
    const int tid = ty * 32 + tx;

#pragma unroll
    for (int i = 0; i < 4; i++) {
        int kk = ty + 32*i;
        s[tx][kk] = W[(size_t)(k0 + kk) * N + n0 + tx];
    }
    __syncthreads();

    const int r = tid >> 5, seg = tid & 31;
    float4 v = *(const float4*)(&s[r][seg << 2]);
    size_t o = ((size_t)(n0 + r) * D_ + k0 + (seg << 2)) >> 2;
    ((uint2*)th)[o] = make_uint2(pack2h(v.x, v.y), pack2h(v.z, v.w));
}

__global__ void wsplit_all_kernel(const float* __restrict__ Wq, const float* __restrict__ Wg,
                                  const float* __restrict__ Wk, const float* __restrict__ Wv,
                                  const float* __restrict__ Wo,
                                  __half* __restrict__ wqg_o, __half* __restrict__ wk,
                                  __half* __restrict__ wv)
{
    const int idx = blockIdx.x;
    if (idx < 1024) {
        wsplit_body(Wq, wqg_o, D_, idx & 63, idx >> 6);
    } else if (idx < 2048) {
        const int i = idx - 1024;
        wsplit_body(Wg, wqg_o + (size_t)D_*D_, D_, i & 63, i >> 6);
    } else if (idx < 2304) {
        const int i = idx - 2048;
        wsplit_body(Wk, wk, 512, i & 15, i >> 4);
    } else if (idx < 2560) {
        const int i = idx - 2304;
        wsplit_body(Wv, wv, 512, i & 15, i >> 4);
    } else {
        const int i = idx - 2560;
        wsplit_body(Wo, wqg_o + (size_t)2*D_*D_, D_, i & 63, i >> 6);
    }
}

#define GK  2048
#define NCH (GK/64)

// ============ BIG GEMM body: 256x128 block, 64x64 warps, single fp16 =======
#define BG_A     32768
#define BG_B     16384
#define BG_STAGE (BG_A + BG_B)
#define BG_SMEM  (2*BG_STAGE + 1024)

__device__ __forceinline__ void gemm_big_body(
    const __half* __restrict__ ah,
    const __half* __restrict__ wth,
    float* __restrict__ C0, float* __restrict__ C1, int cstride,
    int m0, int n0, char* sm)
{
    const uint32_t smb   = smem_u32(sm);
    const uint32_t tiles = (smb + 1023u) & ~1023u;

    const int tid  = threadIdx.x;
    const int wid  = tid >> 5, lane = tid & 31;
    const int wm   = wid & 3,  wn   = wid >> 2;

    const __half* pAh = ah  + (size_t)m0 * GK;
    const __half* pB  = wth + (size_t)n0 * GK;

    float acc[4][8][4];
#pragma unroll
    for (int i = 0; i < 4; i++)
#pragma unroll
        for (int j = 0; j < 8; j++)
#pragma unroll
            for (int q = 0; q < 4; q++) acc[i][j][q] = 0.f;

    auto prefetch = [&](int ch) {
        const uint32_t stage = tiles + (uint32_t)(ch & 1) * BG_STAGE;
        const int ke = ch << 6;
#pragma unroll
        for (int j = 0; j < 8; j++) {
            int idx = tid + (j << 8);
            int r = idx >> 3, c = idx & 7;
            uint32_t off = sw128((r << 7) + (c << 4));
            cp_async16(stage + off, pAh + (size_t)r * GK + ke + (c << 3));
        }
#pragma unroll
        for (int j = 0; j < 4; j++) {
            int idx = tid + (j << 8);
            int r = idx >> 3, c = idx & 7;
            uint32_t off = sw128((r << 7) + (c << 4));
            cp_async16(stage + BG_A + off, pB + (size_t)r * GK + ke + (c << 3));
        }
        CP_COMMIT();
    };

    prefetch(0);

    for (int ch = 0; ch < NCH; ch++) {
        if (ch + 1 < NCH) { prefetch(ch + 1); CP_WAIT(1); }
        else              { CP_WAIT(0); }
        __syncthreads();

        const uint32_t stage = tiles + (uint32_t)(ch & 1) * BG_STAGE;
        const uint32_t sAh = stage, sB = stage + BG_A;

#pragma unroll
        for (int ks = 0; ks < 4; ks++) {
            const int kb = ks << 5;

            uint32_t ahf[4][4];
#pragma unroll
            for (int mt = 0; mt < 4; mt++) {
                int row = wm*64 + mt*16 + (lane & 15);
                uint32_t off = sw128((uint32_t)(row << 7) + kb + ((lane >> 4) << 4));
                ldsm_x4(ahf[mt], sAh + off);
            }
            const int brow = wn*64 + (lane & 7) + ((lane >> 4) << 3);
            const int bko  = kb + (((lane >> 3) & 1) << 4);
#pragma unroll
            for (int np = 0; np < 4; np++) {
                uint32_t bh[4];
                uint32_t off = sw128((uint32_t)((brow + np*16) << 7) + bko);
                ldsm_x4(bh, sB + off);
#pragma unroll
                for (int mt = 0; mt < 4; mt++) {
                    mma16816(acc[mt][2*np],   ahf[mt], bh);
                    mma16816(acc[mt][2*np+1], ahf[mt], bh + 2);
                }
            }
        }
        __syncthreads();
    }

    float* C = C0;
    int nc = n0;
    if (C1 != nullptr && n0 >= cstride) { C = C1; nc = n0 - cstride; }

    const int er = lane >> 2, ec = (lane & 3) << 1;
#pragma unroll
    for (int mt = 0; mt < 4; mt++) {
        int r0 = m0 + wm*64 + mt*16 + er;
#pragma unroll
        for (int nt = 0; nt < 8; nt++) {
            int c = nc + wn*64 + nt*8 + ec;
            *(float2*)(C + (size_t)r0      * cstride + c) = make_float2(acc[mt][nt][0], acc[mt][nt][1]);
            *(float2*)(C + (size_t)(r0 + 8)* cstride + c) = make_float2(acc[mt][nt][2], acc[mt][nt][3]);
        }
    }
}

__global__ void __launch_bounds__(256, 1) gemm_mma_big(
    const __half* __restrict__ ah,
    const __half* __restrict__ wth,
    float* __restrict__ C0, float* __restrict__ C1, int cstride)
{
    extern __shared__ char sm[];
    gemm_big_body(ah, wth, C0, C1, cstride,
                  blockIdx.y << 8, blockIdx.x << 7, sm);
}

#define QKV_TILES 640
__global__ void __launch_bounds__(256, 1) gemm_mma_qkv(
    const __half* __restrict__ aqh,
    const __half* __restrict__ akh,
    const __half* __restrict__ avh,
    const __half* __restrict__ wqh, const __half* __restrict__ wkh,
    const __half* __restrict__ wvh,
    float* __restrict__ pq, float* __restrict__ pg,
    float* __restrict__ pk, float* __restrict__ pv)
{
    extern __shared__ char sm[];
    const int idx = blockIdx.x;
    if (idx < 512) {
        gemm_big_body(aqh, wqh, pq, pg, D_,
                      (idx >> 5) << 8, (idx & 31) << 7, sm);
    } else if (idx < 576) {
        const int i = idx - 512;
        gemm_big_body(akh, wkh, pk, nullptr, 512,
                      (i >> 2) << 8, (i & 3) << 7, sm);
    } else {
        const int i = idx - 576;
        gemm_big_body(avh, wvh, pv, nullptr, 512,
                      (i >> 2) << 8, (i & 3) << 7, sm);
    }
}

// ---- fused per-head RMS norm (+RoPE via table), single fp16 output ----
__device__ __forceinline__ void norm_head_body(
    const float* __restrict__ x, int heads, int do_rope, float scale,
    const float2* __restrict__ rope,
    __half* __restrict__ oh, int blk)
{
    __shared__ float sbuf[4];
    __shared__ float svals[128];
    const int head = blk % heads;
    const int tok  = blk / heads;
    const int t    = tok % T_;
    const size_t base = (size_t)tok*heads*HD_ + head*HD_;
    const float* p = x + base;
    const int d = threadIdx.x;

    float v  = p[d];
    float ss = v*v;
#pragma unroll
    for (int o = 16; o > 0; o >>= 1) ss += __shfl_xor_sync(0xffffffffu, ss, o);
    if ((d & 31) == 0) sbuf[d >> 5] = ss;
    __syncthreads();
    float tot = sbuf[0] + sbuf[1] + sbuf[2] + sbuf[3];
    float r   = rsqrtf(tot * (1.f/HD_) + 1e-8f);
    float vn  = v * r;
    float f;

    if (do_rope) {
        svals[d] = vn;
        __syncthreads();
        int   j  = d & 63;
        float2 cs = rope[t*64 + j];
        float partner = svals[d ^ 64];
        f = (d < 64) ? (vn*cs.x - partner*cs.y) : (vn*cs.x + partner*cs.y);
    } else {
        f = vn;
    }
    f *= scale;
    oh[base + d] = __float2half_rn(f);
}

#define NQBLK (NTOK*H_)
#define NKBLK (NTOK*KVH_)
__global__ void norm_all_kernel(
    const float* __restrict__ pq, const float* __restrict__ pk, const float* __restrict__ pv,
    const float2* __restrict__ rope,
    __half* __restrict__ qh, __half* __restrict__ kh, __half* __restrict__ vh)
{
    const int blk = blockIdx.x;
    if (blk < NQBLK) {
        norm_head_body(pq, H_, 1, 0.08838834764831845f, rope, qh, blk);
    } else if (blk < NQBLK + NKBLK) {
        norm_head_body(pk, KVH_, 1, 1.f, rope, kh, blk - NQBLK);
    } else {
        norm_head_body(pv, KVH_, 0, 1.f, rope, vh, blk - NQBLK - NKBLK);
    }
}

// ============ flash attention: Q/K/V/P all single fp16 ====================
#define FQH  0
#define FKV  32768
#define FSTG 32768
#define FLASH_SMEM (FKV + 2*FSTG)

__global__ void __launch_bounds__(256, 1) flash_mma_kernel(
    const __half* __restrict__ qh,
    const __half* __restrict__ kh, const __half* __restrict__ vh,
    const float* __restrict__ g,
    __half* __restrict__ oh_out)
{
    extern __shared__ char sm[];
    const uint32_t smb = smem_u32(sm);

    const int tid  = threadIdx.x;
    const int w    = tid >> 5, lane = tid & 31;
    const int qt   = (gridDim.x - 1) - blockIdx.x;
    const int b    = blockIdx.y >> 4;
    const int h    = blockIdx.y & 15;
    const int kvh  = h >> 2;
    const int qs   = qt << 7;

    {
        const __half* qg = qh + ((size_t)(b*T_ + qs))*D_ + h*HD_;
#pragma unroll
        for (int it = 0; it < 8; it++) {
            int idx = tid + (it << 8);
            int r = idx >> 4, c = idx & 15;
            cp_async16(smb + FQH + sw256((r << 8) + (c << 4)),
                       qg + (size_t)r*D_ + (c << 3));
        }
        CP_COMMIT();
    }

    const __half* kh_b = kh + (size_t)(b*T_)*(KVH_*HD_) + kvh*HD_;
    const __half* vh_b = vh + (size_t)(b*T_)*(KVH_*HD_) + kvh*HD_;

    auto prefetch_kv = [&](int kt) {
        const uint32_t sb = smb + FKV + (uint32_t)(kt & 1)*FSTG;
        const size_t rb = (size_t)(kt << 6) * (KVH_*HD_);
        const __half* ps[2] = { kh_b + rb, vh_b + rb };
#pragma unroll
        for (int t = 0; t < 2; t++) {
#pragma unroll
            for (int it = 0; it < 4; it++) {
                int idx = tid + (it << 8);
                int r = idx >> 4, c = idx & 15;
                cp_async16(sb + t*16384 + sw256((r << 8) + (c << 4)),
                           ps[t] + (size_t)r*(KVH_*HD_) + (c << 3));
            }
        }
        CP_COMMIT();
    };

    prefetch_kv(0);

    uint32_t aQh[8][4];
    CP_WAIT(1);
    __syncthreads();
#pragma unroll
    for (int ks8 = 0; ks8 < 8; ks8++) {
        int row = (w << 4) + (lane & 15);
        uint32_t off = sw256((uint32_t)(row << 8) + (ks8 << 5) + ((lane >> 4) << 4));
        ldsm_x4(aQh[ks8], smb + FQH + off);
    }

    float o[16][4];
#pragma unroll
    for (int nh = 0; nh < 16; nh++)
#pragma unroll
        for (int qq = 0; qq < 4; qq++) o[nh][qq] = 0.f;
    float m0 = -1e30f, m1 = -1e30f, l0 = 0.f, l1 = 0.f;

    const int nkv = 2*qt + 2;
    for (int kt = 0; kt < nkv; kt++) {
        const int ks = kt << 6;
        if (kt + 1 < nkv) { prefetch_kv(kt + 1); CP_WAIT(1); }
        else              { CP_WAIT(0); }
        __syncthreads();

        const uint32_t sb  = smb + FKV + (uint32_t)(kt & 1)*FSTG;
        const uint32_t sKH = sb, sVH = sb + 16384;

        float s[8][4];
#pragma unroll
        for (int nt = 0; nt < 8; nt++)
#pragma unroll
            for (int qq = 0; qq < 4; qq++) s[nt][qq] = 0.f;

#pragma unroll
        for (int ks8 = 0; ks8 < 8; ks8++) {
            const int kb = ks8 << 5;
            uint32_t bhf[4][4];
            const int brow4 = (lane & 7) + ((lane >> 4) << 3);
            const int bko   = kb + (((lane >> 3) & 1) << 4);
#pragma unroll
            for (int np = 0; np < 4; np++) {
                uint32_t off = sw256((uint32_t)((brow4 + np*16) << 8) + bko);
                ldsm_x4(bhf[np], sKH + off);
            }
#pragma unroll
            for (int np = 0; np < 4; np++) {
                mma16816(s[2*np],   aQh[ks8], bhf[np]);
                mma16816(s[2*np+1], aQh[ks8], bhf[np] + 2);
            }
        }

        if (kt >= 2*qt) {
            const int gr0 = qs + (w << 4) + (lane >> 2);
            const int gc0 = ks + ((lane & 3) << 1);
#pragma unroll
            for (int nt = 0; nt < 8; nt++) {
                int c = gc0 + nt*8;
                if (c     > gr0)     s[nt][0] = -1e30f;
                if (c + 1 > gr0)     s[nt][1] = -1e30f;
                if (c     > gr0 + 8) s[nt][2] = -1e30f;
                if (c + 1 > gr0 + 8) s[nt][3] = -1e30f;
            }
        }

        float mx0 = -1e30f, mx1 = -1e30f;
#pragma unroll
        for (int nt = 0; nt < 8; nt++) {
            mx0 = fmaxf(mx0, fmaxf(s[nt][0], s[nt][1]));
            mx1 = fmaxf(mx1, fmaxf(s[nt][2], s[nt][3]));
        }
        mx0 = fmaxf(mx0, __shfl_xor_sync(0xffffffffu, mx0, 1));
        mx0 = fmaxf(mx0, __shfl_xor_sync(0xffffffffu, mx0, 2));
        mx1 = fmaxf(mx1, __shfl_xor_sync(0xffffffffu, mx1, 1));
        mx1 = fmaxf(mx1, __shfl_xor_sync(0xffffffffu, mx1, 2));
        float m0n = fmaxf(m0, mx0), m1n = fmaxf(m1, mx1);
        float sc0 = fast_exp(m0 - m0n), sc1 = fast_exp(m1 - m1n);
        m0 = m0n; m1 = m1n;

        float sum0 = 0.f, sum1 = 0.f;
#pragma unroll
        for (int nt = 0; nt < 8; nt++) {
            s[nt][0] = fast_exp(s[nt][0] - m0n); sum0 += s[nt][0];
            s[nt][1] = fast_exp(s[nt][1] - m0n); sum0 += s[nt][1];
            s[nt][2] = fast_exp(s[nt][2] - m1n); sum1 += s[nt][2];
            s[nt][3] = fast_exp(s[nt][3] - m1n); sum1 += s[nt][3];
        }
        sum0 += __shfl_xor_sync(0xffffffffu, sum0, 1);
        sum0 += __shfl_xor_sync(0xffffffffu, sum0, 2);
        sum1 += __shfl_xor_sync(0xffffffffu, sum1, 1);
        sum1 += __shfl_xor_sync(0xffffffffu, sum1, 2);
        l0 = l0*sc0 + sum0;
        l1 = l1*sc1 + sum1;

#pragma unroll
        for (int nh = 0; nh < 16; nh++) {
            o[nh][0] *= sc0; o[nh][1] *= sc0;
            o[nh][2] *= sc1; o[nh][3] *= sc1;
        }

        // ---- O += P V (P single fp16) ----
#pragma unroll
        for (int j = 0; j < 4; j++) {
            uint32_t aP[4];
            aP[0] = pack2h(s[2*j][0],   s[2*j][1]);
            aP[1] = pack2h(s[2*j][2],   s[2*j][3]);
            aP[2] = pack2h(s[2*j+1][0], s[2*j+1][1]);
            aP[3] = pack2h(s[2*j+1][2], s[2*j+1][3]);
            const uint32_t vrow = (j << 4) + (lane & 15);
            const uint32_t nsel = (lane >> 4);
#pragma unroll
            for (int pp = 0; pp < 4; pp++) {
                uint32_t bh0[4], bh1[4];
                uint32_t off0 = sw256((vrow << 8) + ((4*pp     + nsel) << 4));
                uint32_t off1 = sw256((vrow << 8) + ((4*pp + 2 + nsel) << 4));
                ldsm_x4_t(bh0, sVH + off0);
                ldsm_x4_t(bh1, sVH + off1);
                mma16816(o[4*pp],   aP, bh0);
                mma16816(o[4*pp+1], aP, bh0 + 2);
                mma16816(o[4*pp+2], aP, bh1);
                mma16816(o[4*pp+3], aP, bh1 + 2);
            }
        }
        __syncthreads();
    }

    // ---- fused epilogue: 1/l, per-head L2 norm, gate, single fp16 out ----
    const float inv0 = 1.f / l0, inv1 = 1.f / l1;
    float y0[16][2], y1[16][2];
    float ss0 = 0.f, ss1 = 0.f;
#pragma unroll
    for (int nh = 0; nh < 16; nh++) {
        y0[nh][0] = o[nh][0]*inv0;  y0[nh][1] = o[nh][1]*inv0;
        y1[nh][0] = o[nh][2]*inv1;  y1[nh][1] = o[nh][3]*inv1;
        ss0 += y0[nh][0]*y0[nh][0] + y0[nh][1]*y0[nh][1];
        ss1 += y1[nh][0]*y1[nh][0] + y1[nh][1]*y1[nh][1];
    }
    ss0 += __shfl_xor_sync(0xffffffffu, ss0, 1);
    ss0 += __shfl_xor_sync(0xffffffffu, ss0, 2);
    ss1 += __shfl_xor_sync(0xffffffffu, ss1, 1);
    ss1 += __shfl_xor_sync(0xffffffffu, ss1, 2);
    const float s0 = 1.f / fmaxf(sqrtf(ss0), 1e-12f);
    const float s1 = 1.f / fmaxf(sqrtf(ss1), 1e-12f);

    const int r0 = qs + (w << 4) + (lane >> 2);
    const size_t base0 = ((size_t)(b*T_) + r0)*D_ + h*HD_ + ((lane & 3) << 1);
    const size_t base1 = base0 + (size_t)8*D_;
#pragma unroll
    for (int nh = 0; nh < 16; nh++) {
        float2 gv0 = *(const float2*)(g + base0 + nh*8);
        float2 gv1 = *(const float2*)(g + base1 + nh*8);
        *(uint32_t*)(oh_out + base0 + nh*8) =
            pack2h(gv0.x*y0[nh][0]*s0, gv0.y*y0[nh][1]*s0);
        *(uint32_t*)(oh_out + base1 + nh*8) =
            pack2h(gv1.x*y1[nh][0]*s1, gv1.y*y1[nh][1]*s1);
    }
}

// ---------------- final RMS norm over D, scaled by 1/sqrt(48) ----------------
__global__ void final_norm_kernel(const float* __restrict__ in, float* __restrict__ out)
{
    __shared__ float sbuf[8];
    const int tok = blockIdx.x;
    const float* p = in + (size_t)tok*D_;
    const int base = threadIdx.x * 8;

    float4 a = *(const float4*)(p + base);
    float4 b = *(const float4*)(p + base + 4);
    float ss = a.x*a.x + a.y*a.y + a.z*a.z + a.w*a.w
             + b.x*b.x + b.y*b.y + b.z*b.z + b.w*b.w;
#pragma unroll
    for (int o = 16; o > 0; o >>= 1) ss += __shfl_xor_sync(0xffffffffu, ss, o);
    if ((threadIdx.x & 31) == 0) sbuf[threadIdx.x >> 5] = ss;
    __syncthreads();
    float tot = 0.f;
#pragma unroll
    for (int i = 0; i < 8; i++) tot += sbuf[i];
    float r = rsqrtf(tot * (1.f/D_) + 1e-8f) * 0.14433756729740643f;

    float* q = out + (size_t)tok*D_;
    a.x*=r; a.y*=r; a.z*=r; a.w*=r;
    b.x*=r; b.y*=r; b.z*=r; b.w*=r;
    *(float4*)(q + base)     = a;
    *(float4*)(q + base + 4) = b;
}

// ---------------- launcher ----------------
extern "C" void kernel_launch(void* const* d_in, const int* in_sizes, int n_in,
                              void* d_out, int out_size)
{
    (void)in_sizes; (void)n_in; (void)out_size;
    const float* xq = (const float*)d_in[0];
    const float* xk = (const float*)d_in[1];
    const float* xv = (const float*)d_in[2];
    const float* Wq = (const float*)d_in[3];
    const float* Wk = (const float*)d_in[4];
    const float* Wv = (const float*)d_in[5];
    const float* Wg = (const float*)d_in[6];
    const float* Wo = (const float*)d_in[7];
    const float* mk = (const float*)d_in[8];
    const float* mv = (const float*)d_in[9];
    float* out = (float*)d_out;

    float *pq, *pk, *pv, *pg, *po;
    __half *pah, *pakh, *pavh, *pwth, *pwkh, *pwvh;
    __half *pqh, *pkh, *pvh;
    float2* prope;
    cudaGetSymbolAddress((void**)&pq,   g_q);
    cudaGetSymbolAddress((void**)&pk,   g_k);
    cudaGetSymbolAddress((void**)&pv,   g_v);
    cudaGetSymbolAddress((void**)&pg,   g_g);
    cudaGetSymbolAddress((void**)&po,   g_o);
    cudaGetSymbolAddress((void**)&pah,  g_ah);
    cudaGetSymbolAddress((void**)&pakh, g_akh);
    cudaGetSymbolAddress((void**)&pavh, g_avh);
    cudaGetSymbolAddress((void**)&pwth, g_wth);
    cudaGetSymbolAddress((void**)&pwkh, g_wkth);
    cudaGetSymbolAddress((void**)&pwvh, g_wvth);
    cudaGetSymbolAddress((void**)&pqh,  g_qh);
    cudaGetSymbolAddress((void**)&pkh,  g_kh);
    cudaGetSymbolAddress((void**)&pvh,  g_vh);
    cudaGetSymbolAddress((void**)&prope, g_rope);

    cudaFuncSetAttribute(gemm_mma_big, cudaFuncAttributeMaxDynamicSharedMemorySize,
                         BG_SMEM);
    cudaFuncSetAttribute(gemm_mma_qkv, cudaFuncAttributeMaxDynamicSharedMemorySize,
                         BG_SMEM);
    cudaFuncSetAttribute(flash_mma_kernel, cudaFuncAttributeMaxDynamicSharedMemorySize,
                         FLASH_SMEM);

    const int XS_GRID = (NTOK*D_/4)/256;

    // 1) RoPE table + fused mix/pack + merged weight transposes
    rope_fill_kernel<<<(T_*64)/256, 256>>>(prope);
    mix_split_kernel<<<XS_GRID, 256>>>(xq, xk, xv, mk, mv, pah, pakh, pavh);
    wsplit_all_kernel<<<3584, dim3(32, 32)>>>(Wq, Wg, Wk, Wv, Wo,
                                              pwth, pwkh, pwvh);

    // 2) fused q/k/v/g projections (single fp16)
    gemm_mma_qkv<<<QKV_TILES, 256, BG_SMEM>>>(
        pah, pakh, pavh, pwth, pwkh, pwvh,
        pq, pg, pk, pv);

    // 3) fused per-head RMS norm (+RoPE via table)
    norm_all_kernel<<<NQBLK + 2*NKBLK, 128>>>(pq, pk, pv, prope,
                                              pqh, pkh, pvh);

    // 4) causal GQA attention + fused L2-norm/gate epilogue
    flash_mma_kernel<<<dim3(T_/128, B_*H_), 256, FLASH_SMEM>>>(
        pqh, pkh, pvh, pg, pah);

    // 5) output projection
    gemm_mma_big<<<dim3(D_/128, NTOK/256), 256, BG_SMEM>>>(
        pah, pwth + (size_t)2*D_*D_, po, nullptr, D_);

    // 6) final RMS norm + 1/sqrt(2*N_LAYER)
    final_norm_kernel<<<NTOK, 256>>>(po, out);
}